// round 1
// baseline (speedup 1.0000x reference)
#include <cuda_runtime.h>
#include <math.h>

#define BATCH  4
#define SEQ    2048
#define DMODEL 1024
#define NHEAD  16
#define DK     64
#define MROWS  (BATCH*SEQ)   // 8192

// ---------------- scratch (device globals: allocation-free rule) ----------------
__device__ float g_q[(size_t)MROWS * DMODEL];
__device__ float g_k[(size_t)MROWS * DMODEL];
__device__ float g_v[(size_t)MROWS * DMODEL];
__device__ float g_ctx[(size_t)MROWS * DMODEL];

// ---------------- SGEMM-NT:  C[M,N] = A[M,K] * W[N,K]^T  (K contiguous both) ----
#define GBM 128
#define GBN 128
#define GBK 16
#define GPAD 132   // GBM + 4 : keeps float4 smem reads aligned, kills most conflicts

__device__ __forceinline__ void gemm_nt_body(const float* __restrict__ A,
                                             const float* __restrict__ W,
                                             float* __restrict__ C)
{
    __shared__ float As[GBK * GPAD];
    __shared__ float Bs[GBK * GPAD];

    const int tid  = threadIdx.x;         // 256 threads
    const int tx   = tid & 15;            // N-dir, 16
    const int ty   = tid >> 4;            // M-dir, 16
    const int brow = blockIdx.y * GBM;
    const int bcol = blockIdx.x * GBN;

    float acc[8][8];
    #pragma unroll
    for (int i = 0; i < 8; i++)
        #pragma unroll
        for (int j = 0; j < 8; j++) acc[i][j] = 0.f;

    for (int k0 = 0; k0 < DMODEL; k0 += GBK) {
        // load 128x16 tiles of A and W, transposed into smem [k][m]
        #pragma unroll
        for (int l = 0; l < 2; l++) {
            int f  = tid + l * 256;       // 0..511
            int r  = f >> 2;              // 0..127
            int c4 = (f & 3) << 2;        // 0,4,8,12
            float4 va = *(const float4*)(A + (size_t)(brow + r) * DMODEL + k0 + c4);
            As[(c4 + 0) * GPAD + r] = va.x;
            As[(c4 + 1) * GPAD + r] = va.y;
            As[(c4 + 2) * GPAD + r] = va.z;
            As[(c4 + 3) * GPAD + r] = va.w;
            float4 vb = *(const float4*)(W + (size_t)(bcol + r) * DMODEL + k0 + c4);
            Bs[(c4 + 0) * GPAD + r] = vb.x;
            Bs[(c4 + 1) * GPAD + r] = vb.y;
            Bs[(c4 + 2) * GPAD + r] = vb.z;
            Bs[(c4 + 3) * GPAD + r] = vb.w;
        }
        __syncthreads();

        #pragma unroll
        for (int k = 0; k < GBK; k++) {
            float4 a0 = *(const float4*)&As[k * GPAD + ty * 8];
            float4 a1 = *(const float4*)&As[k * GPAD + ty * 8 + 4];
            float4 b0 = *(const float4*)&Bs[k * GPAD + tx * 8];
            float4 b1 = *(const float4*)&Bs[k * GPAD + tx * 8 + 4];
            float ra[8] = {a0.x, a0.y, a0.z, a0.w, a1.x, a1.y, a1.z, a1.w};
            float rb[8] = {b0.x, b0.y, b0.z, b0.w, b1.x, b1.y, b1.z, b1.w};
            #pragma unroll
            for (int i = 0; i < 8; i++)
                #pragma unroll
                for (int j = 0; j < 8; j++)
                    acc[i][j] += ra[i] * rb[j];
        }
        __syncthreads();
    }

    #pragma unroll
    for (int i = 0; i < 8; i++) {
        size_t row = (size_t)(brow + ty * 8 + i);
        float4 v0 = make_float4(acc[i][0], acc[i][1], acc[i][2], acc[i][3]);
        float4 v1 = make_float4(acc[i][4], acc[i][5], acc[i][6], acc[i][7]);
        *(float4*)(C + row * DMODEL + bcol + tx * 8)     = v0;
        *(float4*)(C + row * DMODEL + bcol + tx * 8 + 4) = v1;
    }
}

__global__ void __launch_bounds__(256)
gemm_qkv_kernel(const float* __restrict__ x,
                const float* __restrict__ wq,
                const float* __restrict__ wk,
                const float* __restrict__ wv)
{
    int z = blockIdx.z;
    const float* W = (z == 0) ? wq : (z == 1) ? wk : wv;
    float*       C = (z == 0) ? g_q : (z == 1) ? g_k : g_v;
    gemm_nt_body(x, W, C);
}

__global__ void __launch_bounds__(256)
gemm_out_kernel(const float* __restrict__ wo, float* __restrict__ out)
{
    gemm_nt_body(g_ctx, wo, out);
}

// ---------------- Flash attention (causal), 64x64 tiles, fp32 -------------------
#define AT   64
#define APAD 65
#define QK_SCALE 0.125f   // 1/sqrt(64)

__global__ void __launch_bounds__(256)
attn_kernel()
{
    extern __shared__ float sm[];
    float* Qs   = sm;                    // [64][65] rows x d
    float* Ss   = Qs + AT * APAD;        // [64][65] scores / probs
    float* Ks   = Ss + AT * APAD;        // [64][65] TRANSPOSED: [d][c]
    float* Vs   = Ks + AT * APAD;        // [64][65] rows(c) x d
    float* m_sm = Vs + AT * APAD;        // [64] running max
    float* l_sm = m_sm + AT;             // [64] running denom
    float* a_sm = l_sm + AT;             // [64] rescale factor

    const int tid = threadIdx.x;         // 256 threads = 16x16
    const int tx  = tid & 15;
    const int ty  = tid >> 4;
    const int qb  = blockIdx.x;          // query block (0..31)
    const int bh  = blockIdx.y;          // b*H + h
    const int b   = bh >> 4;
    const int h   = bh & 15;

    const size_t base = (size_t)b * SEQ * DMODEL + (size_t)h * DK;
    const float* Qg = g_q   + base;      // row stride DMODEL
    const float* Kg = g_k   + base;
    const float* Vg = g_v   + base;
    float*       Og = g_ctx + base;

    // load Q tile (pre-scaled)
    #pragma unroll
    for (int l = 0; l < 4; l++) {
        int f  = tid + l * 256;          // 0..1023
        int r  = f >> 4;                 // 0..63
        int d0 = (f & 15) << 2;          // 0..60
        float4 v = *(const float4*)(Qg + (size_t)(qb * AT + r) * DMODEL + d0);
        Qs[r * APAD + d0 + 0] = v.x * QK_SCALE;
        Qs[r * APAD + d0 + 1] = v.y * QK_SCALE;
        Qs[r * APAD + d0 + 2] = v.z * QK_SCALE;
        Qs[r * APAD + d0 + 3] = v.w * QK_SCALE;
    }
    if (tid < AT) { m_sm[tid] = -1e30f; l_sm[tid] = 0.f; }

    float o[4][4];
    #pragma unroll
    for (int i = 0; i < 4; i++)
        #pragma unroll
        for (int j = 0; j < 4; j++) o[i][j] = 0.f;

    __syncthreads();

    for (int kb = 0; kb <= qb; kb++) {
        // load K (transposed into [d][c]) and V ([c][d])
        #pragma unroll
        for (int l = 0; l < 4; l++) {
            int f  = tid + l * 256;
            int c  = f >> 4;
            int d0 = (f & 15) << 2;
            const size_t grow = (size_t)(kb * AT + c) * DMODEL + d0;
            float4 kv = *(const float4*)(Kg + grow);
            Ks[(d0 + 0) * APAD + c] = kv.x;
            Ks[(d0 + 1) * APAD + c] = kv.y;
            Ks[(d0 + 2) * APAD + c] = kv.z;
            Ks[(d0 + 3) * APAD + c] = kv.w;
            float4 vv = *(const float4*)(Vg + grow);
            Vs[c * APAD + d0 + 0] = vv.x;
            Vs[c * APAD + d0 + 1] = vv.y;
            Vs[c * APAD + d0 + 2] = vv.z;
            Vs[c * APAD + d0 + 3] = vv.w;
        }
        __syncthreads();

        // S = Q K^T   (thread: rows ty*4.., cols tx*4..)
        float sacc[4][4];
        #pragma unroll
        for (int i = 0; i < 4; i++)
            #pragma unroll
            for (int j = 0; j < 4; j++) sacc[i][j] = 0.f;

        #pragma unroll 8
        for (int d = 0; d < AT; d++) {
            float qa[4], kv[4];
            #pragma unroll
            for (int i = 0; i < 4; i++) qa[i] = Qs[(ty * 4 + i) * APAD + d];
            #pragma unroll
            for (int j = 0; j < 4; j++) kv[j] = Ks[d * APAD + tx * 4 + j];
            #pragma unroll
            for (int i = 0; i < 4; i++)
                #pragma unroll
                for (int j = 0; j < 4; j++)
                    sacc[i][j] += qa[i] * kv[j];
        }

        if (kb == qb) {
            #pragma unroll
            for (int i = 0; i < 4; i++)
                #pragma unroll
                for (int j = 0; j < 4; j++) {
                    int qr = ty * 4 + i, kc = tx * 4 + j;
                    Ss[qr * APAD + kc] = (kc <= qr) ? sacc[i][j] : -1e30f;
                }
        } else {
            #pragma unroll
            for (int i = 0; i < 4; i++)
                #pragma unroll
                for (int j = 0; j < 4; j++)
                    Ss[(ty * 4 + i) * APAD + tx * 4 + j] = sacc[i][j];
        }
        __syncthreads();

        // online softmax, one thread per row
        if (tid < AT) {
            const int r = tid;
            float mold = m_sm[r];
            float mnew = mold;
            #pragma unroll 8
            for (int c = 0; c < AT; c++) mnew = fmaxf(mnew, Ss[r * APAD + c]);
            float a = __expf(mold - mnew);
            float sum = 0.f;
            #pragma unroll 8
            for (int c = 0; c < AT; c++) {
                float p = __expf(Ss[r * APAD + c] - mnew);
                Ss[r * APAD + c] = p;
                sum += p;
            }
            l_sm[r] = l_sm[r] * a + sum;
            m_sm[r] = mnew;
            a_sm[r] = a;
        }
        __syncthreads();

        // rescale O, accumulate O += P V
        float av[4];
        #pragma unroll
        for (int i = 0; i < 4; i++) av[i] = a_sm[ty * 4 + i];
        #pragma unroll
        for (int i = 0; i < 4; i++)
            #pragma unroll
            for (int j = 0; j < 4; j++) o[i][j] *= av[i];

        #pragma unroll 8
        for (int c = 0; c < AT; c++) {
            float pa[4], vb[4];
            #pragma unroll
            for (int i = 0; i < 4; i++) pa[i] = Ss[(ty * 4 + i) * APAD + c];
            #pragma unroll
            for (int j = 0; j < 4; j++) vb[j] = Vs[c * APAD + tx * 4 + j];
            #pragma unroll
            for (int i = 0; i < 4; i++)
                #pragma unroll
                for (int j = 0; j < 4; j++)
                    o[i][j] += pa[i] * vb[j];
        }
        __syncthreads();   // guard smem reuse before next tile's loads
    }

    // epilogue: normalize by running denom, write context
    #pragma unroll
    for (int i = 0; i < 4; i++) {
        int r = ty * 4 + i;
        float inv = 1.f / fmaxf(l_sm[r], 1e-9f);
        float4 v = make_float4(o[i][0] * inv, o[i][1] * inv,
                               o[i][2] * inv, o[i][3] * inv);
        *(float4*)(Og + (size_t)(qb * AT + r) * DMODEL + tx * 4) = v;
    }
}

// ---------------- launch ---------------------------------------------------------
static const size_t ATTN_SMEM = (size_t)(4 * AT * APAD + 3 * AT) * sizeof(float);

extern "C" void kernel_launch(void* const* d_in, const int* in_sizes, int n_in,
                              void* d_out, int out_size)
{
    (void)in_sizes; (void)n_in; (void)out_size;
    const float* x  = (const float*)d_in[0];
    const float* wq = (const float*)d_in[1];
    const float* wk = (const float*)d_in[2];
    const float* wv = (const float*)d_in[3];
    const float* wo = (const float*)d_in[4];
    float* out = (float*)d_out;

    // one-time opt-in (>48KB dyn smem); first call is the uncaptured correctness run
    static cudaError_t attr_once = cudaFuncSetAttribute(
        attn_kernel, cudaFuncAttributeMaxDynamicSharedMemorySize, (int)ATTN_SMEM);
    (void)attr_once;

    dim3 gqkv(DMODEL / GBN, MROWS / GBM, 3);
    gemm_qkv_kernel<<<gqkv, 256>>>(x, wq, wk, wv);

    dim3 gattn(SEQ / AT, BATCH * NHEAD);
    attn_kernel<<<gattn, 256, ATTN_SMEM>>>();

    dim3 gout(DMODEL / GBN, MROWS / GBM);
    gemm_out_kernel<<<gout, 256>>>(wo, out);
}

// round 3
// speedup vs baseline: 1.3900x; 1.3900x over previous
#include <cuda_runtime.h>
#include <cuda_bf16.h>
#include <cstdint>
#include <math.h>

#define BATCH  4
#define SEQ    2048
#define DMODEL 1024
#define NHEAD  16
#define DK     64
#define MROWS  (BATCH*SEQ)   // 8192

// ---------------- scratch (device globals: allocation-free rule) ----------------
__device__ float g_q[(size_t)MROWS * DMODEL];
__device__ float g_k[(size_t)MROWS * DMODEL];
__device__ float g_v[(size_t)MROWS * DMODEL];
__device__ float g_ctx[(size_t)MROWS * DMODEL];

__device__ __nv_bfloat16 g_xh[(size_t)MROWS * DMODEL];
__device__ __nv_bfloat16 g_xl[(size_t)MROWS * DMODEL];
__device__ __nv_bfloat16 g_ch[(size_t)MROWS * DMODEL];
__device__ __nv_bfloat16 g_cl[(size_t)MROWS * DMODEL];
__device__ __nv_bfloat16 g_wh[4][(size_t)DMODEL * DMODEL];
__device__ __nv_bfloat16 g_wl[4][(size_t)DMODEL * DMODEL];

// ================= PTX helpers (portable: sm_80-class only) ====================
__device__ __forceinline__ uint32_t smem_u32(const void* p) {
    uint32_t a;
    asm("{ .reg .u64 t; cvta.to.shared.u64 t, %1; cvt.u32.u64 %0, t; }" : "=r"(a) : "l"(p));
    return a;
}
template <int N> __device__ __forceinline__ void cp_wait_group() {
    asm volatile("cp.async.wait_group %0;" :: "n"(N) : "memory");
}
__device__ __forceinline__ void cp_commit_group() {
    asm volatile("cp.async.commit_group;" ::: "memory");
}
__device__ __forceinline__ void cp_async16(uint32_t dst, const void* src) {
    asm volatile("cp.async.cg.shared.global [%0], [%1], 16;" :: "r"(dst), "l"(src) : "memory");
}
__device__ __forceinline__ void ldsm4(uint32_t* r, uint32_t addr) {
    asm volatile("ldmatrix.sync.aligned.m8n8.x4.shared.b16 {%0,%1,%2,%3}, [%4];"
                 : "=r"(r[0]), "=r"(r[1]), "=r"(r[2]), "=r"(r[3]) : "r"(addr));
}
__device__ __forceinline__ void mma16816(float* c, const uint32_t* a, const uint32_t* b) {
    asm volatile(
        "mma.sync.aligned.m16n8k16.row.col.f32.bf16.bf16.f32 "
        "{%0,%1,%2,%3}, {%4,%5,%6,%7}, {%8,%9}, {%0,%1,%2,%3};"
        : "+f"(c[0]), "+f"(c[1]), "+f"(c[2]), "+f"(c[3])
        : "r"(a[0]), "r"(a[1]), "r"(a[2]), "r"(a[3]), "r"(b[0]), "r"(b[1]));
}

// ================= bf16-split GEMM-NT via mma.sync =============================
// C[M,1024] = (Ah+Al)[M,1024] * (Wh+Wl)[1024,1024]^T, fp32 accumulate.
// CTA tile 128x128, BK=32, 8 warps (2x4) of 64x32 warp tiles, 3-stage cp.async.
#define BM 128
#define BN 128
#define BK 32
#define NST 3
#define NCHUNK (DMODEL / BK)        // 32
#define SROW 80                      // bytes per smem row: 32 bf16 + 8 pad
#define TILE_SM (128 * SROW)         // 10240 B
#define STAGE_SM (4 * TILE_SM)       // Ah, Al, Bh, Bl
#define GEMM_SMEM (NST * STAGE_SM)   // 122880 B

__device__ __forceinline__ void ld_tile(const __nv_bfloat16* __restrict__ g,
                                        int rowbase, int k0, uint32_t dst, int tid) {
    #pragma unroll
    for (int l = 0; l < 2; l++) {
        int f = tid + (l << 8);      // 0..511
        int r = f >> 2;              // row 0..127
        int c = f & 3;               // 16B unit (4 per 64B row)
        const __nv_bfloat16* src = g + (size_t)(rowbase + r) * DMODEL + k0 + c * 8;
        cp_async16(dst + r * SROW + c * 16, src);
    }
}

__device__ __forceinline__ void gemm_tc_body(const __nv_bfloat16* __restrict__ Ah,
                                             const __nv_bfloat16* __restrict__ Al,
                                             const __nv_bfloat16* __restrict__ Wh,
                                             const __nv_bfloat16* __restrict__ Wl,
                                             float* __restrict__ C, int tm, int tn) {
    extern __shared__ __align__(128) char smem[];
    const uint32_t sb = smem_u32(smem);
    const int tid  = threadIdx.x;
    const int wid  = tid >> 5;
    const int lane = tid & 31;
    const int wm   = wid >> 2;       // 0..1  (M)
    const int wn   = wid & 3;        // 0..3  (N)

    const int rowA = tm * BM;
    const int rowB = tn * BN;

    float acc[4][4][4];
    #pragma unroll
    for (int i = 0; i < 4; i++)
        #pragma unroll
        for (int j = 0; j < 4; j++)
            #pragma unroll
            for (int e = 0; e < 4; e++) acc[i][j][e] = 0.f;

    // ldmatrix source addresses (per-lane, relative to tile base)
    const uint32_t a_off = (uint32_t)((wm * 64 + (lane & 15)) * SROW + (lane >> 4) * 16);
    const uint32_t b_off = (uint32_t)((wn * 32 + (lane >> 4) * 8 + (lane & 7)) * SROW
                                      + ((lane >> 3) & 1) * 16);

    // prologue
    #pragma unroll
    for (int s = 0; s < NST; s++) {
        uint32_t st = sb + s * STAGE_SM;
        ld_tile(Ah, rowA, s * BK, st + 0 * TILE_SM, tid);
        ld_tile(Al, rowA, s * BK, st + 1 * TILE_SM, tid);
        ld_tile(Wh, rowB, s * BK, st + 2 * TILE_SM, tid);
        ld_tile(Wl, rowB, s * BK, st + 3 * TILE_SM, tid);
        cp_commit_group();
    }

    for (int c = 0; c < NCHUNK; c++) {
        cp_wait_group<NST - 1>();
        __syncthreads();

        const uint32_t st = sb + (c % NST) * STAGE_SM;
        #pragma unroll
        for (int ks = 0; ks < 2; ks++) {
            const uint32_t kb = ks * 32;   // 16 bf16 = 32 bytes
            // B fragments: bh[8], bl[8] (four n8 frags each, 2 regs per frag)
            uint32_t bh[8], bl[8];
            ldsm4(bh,     st + 2 * TILE_SM + b_off + kb);
            ldsm4(bh + 4, st + 2 * TILE_SM + b_off + kb + 16 * SROW);
            ldsm4(bl,     st + 3 * TILE_SM + b_off + kb);
            ldsm4(bl + 4, st + 3 * TILE_SM + b_off + kb + 16 * SROW);
            #pragma unroll
            for (int mf = 0; mf < 4; mf++) {
                uint32_t ah[4], al[4];
                ldsm4(ah, st + 0 * TILE_SM + a_off + kb + mf * 16 * SROW);
                ldsm4(al, st + 1 * TILE_SM + a_off + kb + mf * 16 * SROW);
                #pragma unroll
                for (int nf = 0; nf < 4; nf++) {
                    mma16816(acc[mf][nf], ah, bh + nf * 2);
                    mma16816(acc[mf][nf], ah, bl + nf * 2);
                    mma16816(acc[mf][nf], al, bh + nf * 2);
                }
            }
        }
        __syncthreads();

        if (c + NST < NCHUNK) {
            int k0 = (c + NST) * BK;
            ld_tile(Ah, rowA, k0, st + 0 * TILE_SM, tid);
            ld_tile(Al, rowA, k0, st + 1 * TILE_SM, tid);
            ld_tile(Wh, rowB, k0, st + 2 * TILE_SM, tid);
            ld_tile(Wl, rowB, k0, st + 3 * TILE_SM, tid);
        }
        cp_commit_group();   // empty group when no loads: keeps wait-count valid
    }

    // epilogue: c-frag layout (m16n8): c0,c1 -> (lane/4, (lane%4)*2), c2,c3 -> +8 rows
    const int r0c = lane >> 2;
    const int cc  = (lane & 3) * 2;
    #pragma unroll
    for (int mf = 0; mf < 4; mf++) {
        const int mrow = rowA + wm * 64 + mf * 16;
        #pragma unroll
        for (int nf = 0; nf < 4; nf++) {
            const int col = rowB + wn * 32 + nf * 8 + cc;
            float2 v0 = make_float2(acc[mf][nf][0], acc[mf][nf][1]);
            float2 v1 = make_float2(acc[mf][nf][2], acc[mf][nf][3]);
            *(float2*)(C + (size_t)(mrow + r0c) * DMODEL + col)     = v0;
            *(float2*)(C + (size_t)(mrow + r0c + 8) * DMODEL + col) = v1;
        }
    }
}

__global__ void __launch_bounds__(256, 1)
gemm_qkv_tc() {
    const int w = blockIdx.z;
    float* C = (w == 0) ? g_q : (w == 1) ? g_k : g_v;
    gemm_tc_body(g_xh, g_xl, g_wh[w], g_wl[w], C, blockIdx.y, blockIdx.x);
}

__global__ void __launch_bounds__(256, 1)
gemm_out_tc(float* __restrict__ out) {
    gemm_tc_body(g_ch, g_cl, g_wh[3], g_wl[3], out, blockIdx.y, blockIdx.x);
}

// ================= fp32 -> bf16 hi/lo split ====================================
__global__ void __launch_bounds__(256)
split_kernel(const float* __restrict__ in, __nv_bfloat16* __restrict__ hi,
             __nv_bfloat16* __restrict__ lo, int n4) {
    __nv_bfloat162* H = (__nv_bfloat162*)hi;
    __nv_bfloat162* L = (__nv_bfloat162*)lo;
    for (int i = blockIdx.x * blockDim.x + threadIdx.x; i < n4;
         i += gridDim.x * blockDim.x) {
        float4 v = ((const float4*)in)[i];
        float a[4] = {v.x, v.y, v.z, v.w};
        __nv_bfloat16 h[4], l[4];
        #pragma unroll
        for (int j = 0; j < 4; j++) {
            h[j] = __float2bfloat16(a[j]);
            l[j] = __float2bfloat16(a[j] - __bfloat162float(h[j]));
        }
        H[2 * i]     = __halves2bfloat162(h[0], h[1]);
        H[2 * i + 1] = __halves2bfloat162(h[2], h[3]);
        L[2 * i]     = __halves2bfloat162(l[0], l[1]);
        L[2 * i + 1] = __halves2bfloat162(l[2], l[3]);
    }
}

// ================= Flash attention (causal), fp32 ==============================
#define AT   64
#define APAD 65
#define QK_SCALE 0.125f

__global__ void __launch_bounds__(256)
attn_kernel() {
    extern __shared__ float sm[];
    float* Qs   = sm;
    float* Ss   = Qs + AT * APAD;
    float* Ks   = Ss + AT * APAD;
    float* Vs   = Ks + AT * APAD;
    float* m_sm = Vs + AT * APAD;
    float* l_sm = m_sm + AT;
    float* a_sm = l_sm + AT;

    const int tid = threadIdx.x;
    const int tx  = tid & 15;
    const int ty  = tid >> 4;
    const int qb  = blockIdx.x;
    const int bh  = blockIdx.y;
    const int b   = bh >> 4;
    const int h   = bh & 15;

    const size_t base = (size_t)b * SEQ * DMODEL + (size_t)h * DK;
    const float* Qg = g_q   + base;
    const float* Kg = g_k   + base;
    const float* Vg = g_v   + base;
    float*       Og = g_ctx + base;

    #pragma unroll
    for (int l = 0; l < 4; l++) {
        int f  = tid + l * 256;
        int r  = f >> 4;
        int d0 = (f & 15) << 2;
        float4 v = *(const float4*)(Qg + (size_t)(qb * AT + r) * DMODEL + d0);
        Qs[r * APAD + d0 + 0] = v.x * QK_SCALE;
        Qs[r * APAD + d0 + 1] = v.y * QK_SCALE;
        Qs[r * APAD + d0 + 2] = v.z * QK_SCALE;
        Qs[r * APAD + d0 + 3] = v.w * QK_SCALE;
    }
    if (tid < AT) { m_sm[tid] = -1e30f; l_sm[tid] = 0.f; }

    float o[4][4];
    #pragma unroll
    for (int i = 0; i < 4; i++)
        #pragma unroll
        for (int j = 0; j < 4; j++) o[i][j] = 0.f;

    __syncthreads();

    for (int kb = 0; kb <= qb; kb++) {
        #pragma unroll
        for (int l = 0; l < 4; l++) {
            int f  = tid + l * 256;
            int c  = f >> 4;
            int d0 = (f & 15) << 2;
            const size_t grow = (size_t)(kb * AT + c) * DMODEL + d0;
            float4 kv = *(const float4*)(Kg + grow);
            Ks[(d0 + 0) * APAD + c] = kv.x;
            Ks[(d0 + 1) * APAD + c] = kv.y;
            Ks[(d0 + 2) * APAD + c] = kv.z;
            Ks[(d0 + 3) * APAD + c] = kv.w;
            float4 vv = *(const float4*)(Vg + grow);
            Vs[c * APAD + d0 + 0] = vv.x;
            Vs[c * APAD + d0 + 1] = vv.y;
            Vs[c * APAD + d0 + 2] = vv.z;
            Vs[c * APAD + d0 + 3] = vv.w;
        }
        __syncthreads();

        float sacc[4][4];
        #pragma unroll
        for (int i = 0; i < 4; i++)
            #pragma unroll
            for (int j = 0; j < 4; j++) sacc[i][j] = 0.f;

        #pragma unroll 8
        for (int d = 0; d < AT; d++) {
            float qa[4], kv[4];
            #pragma unroll
            for (int i = 0; i < 4; i++) qa[i] = Qs[(ty * 4 + i) * APAD + d];
            #pragma unroll
            for (int j = 0; j < 4; j++) kv[j] = Ks[d * APAD + tx * 4 + j];
            #pragma unroll
            for (int i = 0; i < 4; i++)
                #pragma unroll
                for (int j = 0; j < 4; j++)
                    sacc[i][j] += qa[i] * kv[j];
        }

        if (kb == qb) {
            #pragma unroll
            for (int i = 0; i < 4; i++)
                #pragma unroll
                for (int j = 0; j < 4; j++) {
                    int qr = ty * 4 + i, kc = tx * 4 + j;
                    Ss[qr * APAD + kc] = (kc <= qr) ? sacc[i][j] : -1e30f;
                }
        } else {
            #pragma unroll
            for (int i = 0; i < 4; i++)
                #pragma unroll
                for (int j = 0; j < 4; j++)
                    Ss[(ty * 4 + i) * APAD + tx * 4 + j] = sacc[i][j];
        }
        __syncthreads();

        if (tid < AT) {
            const int r = tid;
            float mold = m_sm[r];
            float mnew = mold;
            #pragma unroll 8
            for (int c = 0; c < AT; c++) mnew = fmaxf(mnew, Ss[r * APAD + c]);
            float a = __expf(mold - mnew);
            float sum = 0.f;
            #pragma unroll 8
            for (int c = 0; c < AT; c++) {
                float p = __expf(Ss[r * APAD + c] - mnew);
                Ss[r * APAD + c] = p;
                sum += p;
            }
            l_sm[r] = l_sm[r] * a + sum;
            m_sm[r] = mnew;
            a_sm[r] = a;
        }
        __syncthreads();

        float av[4];
        #pragma unroll
        for (int i = 0; i < 4; i++) av[i] = a_sm[ty * 4 + i];
        #pragma unroll
        for (int i = 0; i < 4; i++)
            #pragma unroll
            for (int j = 0; j < 4; j++) o[i][j] *= av[i];

        #pragma unroll 8
        for (int c = 0; c < AT; c++) {
            float pa[4], vb[4];
            #pragma unroll
            for (int i = 0; i < 4; i++) pa[i] = Ss[(ty * 4 + i) * APAD + c];
            #pragma unroll
            for (int j = 0; j < 4; j++) vb[j] = Vs[c * APAD + tx * 4 + j];
            #pragma unroll
            for (int i = 0; i < 4; i++)
                #pragma unroll
                for (int j = 0; j < 4; j++)
                    o[i][j] += pa[i] * vb[j];
        }
        __syncthreads();
    }

    #pragma unroll
    for (int i = 0; i < 4; i++) {
        int r = ty * 4 + i;
        float inv = 1.f / fmaxf(l_sm[r], 1e-9f);
        float4 v = make_float4(o[i][0] * inv, o[i][1] * inv,
                               o[i][2] * inv, o[i][3] * inv);
        *(float4*)(Og + (size_t)(qb * AT + r) * DMODEL + tx * 4) = v;
    }
}

// ================= launch ======================================================
static const size_t ATTN_SMEM = (size_t)(4 * AT * APAD + 3 * AT) * sizeof(float);

extern "C" void kernel_launch(void* const* d_in, const int* in_sizes, int n_in,
                              void* d_out, int out_size)
{
    (void)in_sizes; (void)n_in; (void)out_size;
    const float* x  = (const float*)d_in[0];
    const float* wq = (const float*)d_in[1];
    const float* wk = (const float*)d_in[2];
    const float* wv = (const float*)d_in[3];
    const float* wo = (const float*)d_in[4];
    float* out = (float*)d_out;

    static cudaError_t a1 = cudaFuncSetAttribute(
        attn_kernel, cudaFuncAttributeMaxDynamicSharedMemorySize, (int)ATTN_SMEM);
    static cudaError_t a2 = cudaFuncSetAttribute(
        gemm_qkv_tc, cudaFuncAttributeMaxDynamicSharedMemorySize, GEMM_SMEM);
    static cudaError_t a3 = cudaFuncSetAttribute(
        gemm_out_tc, cudaFuncAttributeMaxDynamicSharedMemorySize, GEMM_SMEM);
    (void)a1; (void)a2; (void)a3;

    __nv_bfloat16 *xh, *xl, *ch, *cl, *wh, *wl;
    cudaGetSymbolAddress((void**)&xh, g_xh);
    cudaGetSymbolAddress((void**)&xl, g_xl);
    cudaGetSymbolAddress((void**)&ch, g_ch);
    cudaGetSymbolAddress((void**)&cl, g_cl);
    cudaGetSymbolAddress((void**)&wh, g_wh);
    cudaGetSymbolAddress((void**)&wl, g_wl);
    float* ctx;
    cudaGetSymbolAddress((void**)&ctx, g_ctx);

    const int NX = MROWS * DMODEL / 4;
    const int NW = DMODEL * DMODEL / 4;

    split_kernel<<<2048, 256>>>(x, xh, xl, NX);
    split_kernel<<<512, 256>>>(wq, wh + 0 * (size_t)DMODEL * DMODEL, wl + 0 * (size_t)DMODEL * DMODEL, NW);
    split_kernel<<<512, 256>>>(wk, wh + 1 * (size_t)DMODEL * DMODEL, wl + 1 * (size_t)DMODEL * DMODEL, NW);
    split_kernel<<<512, 256>>>(wv, wh + 2 * (size_t)DMODEL * DMODEL, wl + 2 * (size_t)DMODEL * DMODEL, NW);
    split_kernel<<<512, 256>>>(wo, wh + 3 * (size_t)DMODEL * DMODEL, wl + 3 * (size_t)DMODEL * DMODEL, NW);

    dim3 gqkv(DMODEL / BN, MROWS / BM, 3);
    gemm_qkv_tc<<<gqkv, 256, GEMM_SMEM>>>();

    dim3 gattn(SEQ / AT, BATCH * NHEAD);
    attn_kernel<<<gattn, 256, ATTN_SMEM>>>();

    split_kernel<<<2048, 256>>>(ctx, ch, cl, NX);

    dim3 gout(DMODEL / BN, MROWS / BM);
    gemm_out_tc<<<gout, 256, GEMM_SMEM>>>(out);
}

// round 4
// speedup vs baseline: 1.7249x; 1.2409x over previous
#include <cuda_runtime.h>
#include <cuda_bf16.h>
#include <cstdint>
#include <math.h>

#define BATCH  4
#define SEQ    2048
#define DMODEL 1024
#define NHEAD  16
#define DK     64
#define MROWS  (BATCH*SEQ)   // 8192

// ---------------- scratch (device globals: allocation-free rule) ----------------
__device__ __nv_bfloat16 g_xh[(size_t)MROWS * DMODEL];
__device__ __nv_bfloat16 g_xl[(size_t)MROWS * DMODEL];
__device__ __nv_bfloat16 g_qh[(size_t)MROWS * DMODEL];
__device__ __nv_bfloat16 g_ql[(size_t)MROWS * DMODEL];
__device__ __nv_bfloat16 g_kh[(size_t)MROWS * DMODEL];
__device__ __nv_bfloat16 g_kl[(size_t)MROWS * DMODEL];
__device__ __nv_bfloat16 g_vh[(size_t)MROWS * DMODEL];
__device__ __nv_bfloat16 g_vl[(size_t)MROWS * DMODEL];
__device__ __nv_bfloat16 g_ch[(size_t)MROWS * DMODEL];
__device__ __nv_bfloat16 g_cl[(size_t)MROWS * DMODEL];
__device__ __nv_bfloat16 g_wh[4][(size_t)DMODEL * DMODEL];
__device__ __nv_bfloat16 g_wl[4][(size_t)DMODEL * DMODEL];

// ================= PTX helpers (portable sm_80-class only) =====================
__device__ __forceinline__ uint32_t smem_u32(const void* p) {
    uint32_t a;
    asm("{ .reg .u64 t; cvta.to.shared.u64 t, %1; cvt.u32.u64 %0, t; }" : "=r"(a) : "l"(p));
    return a;
}
template <int N> __device__ __forceinline__ void cp_wait_group() {
    asm volatile("cp.async.wait_group %0;" :: "n"(N) : "memory");
}
__device__ __forceinline__ void cp_commit_group() {
    asm volatile("cp.async.commit_group;" ::: "memory");
}
__device__ __forceinline__ void cp_async16(uint32_t dst, const void* src) {
    asm volatile("cp.async.cg.shared.global [%0], [%1], 16;" :: "r"(dst), "l"(src) : "memory");
}
__device__ __forceinline__ void ldsm4(uint32_t* r, uint32_t addr) {
    asm volatile("ldmatrix.sync.aligned.m8n8.x4.shared.b16 {%0,%1,%2,%3}, [%4];"
                 : "=r"(r[0]), "=r"(r[1]), "=r"(r[2]), "=r"(r[3]) : "r"(addr));
}
__device__ __forceinline__ void ldsm4t(uint32_t* r, uint32_t addr) {
    asm volatile("ldmatrix.sync.aligned.m8n8.x4.trans.shared.b16 {%0,%1,%2,%3}, [%4];"
                 : "=r"(r[0]), "=r"(r[1]), "=r"(r[2]), "=r"(r[3]) : "r"(addr));
}
__device__ __forceinline__ void mma16816(float* c, const uint32_t* a, const uint32_t* b) {
    asm volatile(
        "mma.sync.aligned.m16n8k16.row.col.f32.bf16.bf16.f32 "
        "{%0,%1,%2,%3}, {%4,%5,%6,%7}, {%8,%9}, {%0,%1,%2,%3};"
        : "+f"(c[0]), "+f"(c[1]), "+f"(c[2]), "+f"(c[3])
        : "r"(a[0]), "r"(a[1]), "r"(a[2]), "r"(a[3]), "r"(b[0]), "r"(b[1]));
}
__device__ __forceinline__ uint32_t pack_bf16x2(float lo, float hi) {
    __nv_bfloat162 t = __halves2bfloat162(__float2bfloat16(lo), __float2bfloat16(hi));
    return *(uint32_t*)&t;
}

// ================= bf16-split GEMM-NT via mma.sync =============================
#define BM 128
#define BN 128
#define BK 32
#define NST 3
#define NCHUNK (DMODEL / BK)        // 32
#define SROW 80
#define TILE_SM (128 * SROW)
#define STAGE_SM (4 * TILE_SM)
#define GEMM_SMEM (NST * STAGE_SM)   // 122880

__device__ __forceinline__ void ld_tile(const __nv_bfloat16* __restrict__ g,
                                        int rowbase, int k0, uint32_t dst, int tid) {
    #pragma unroll
    for (int l = 0; l < 2; l++) {
        int f = tid + (l << 8);
        int r = f >> 2;
        int c = f & 3;
        const __nv_bfloat16* src = g + (size_t)(rowbase + r) * DMODEL + k0 + c * 8;
        cp_async16(dst + r * SROW + c * 16, src);
    }
}

// mainloop: fills acc[4][4][4]
__device__ __forceinline__ void gemm_core(const __nv_bfloat16* __restrict__ Ah,
                                          const __nv_bfloat16* __restrict__ Al,
                                          const __nv_bfloat16* __restrict__ Wh,
                                          const __nv_bfloat16* __restrict__ Wl,
                                          int rowA, int rowB,
                                          float acc[4][4][4]) {
    extern __shared__ __align__(128) char smem[];
    const uint32_t sb = smem_u32(smem);
    const int tid  = threadIdx.x;
    const int wid  = tid >> 5;
    const int lane = tid & 31;
    const int wm   = wid >> 2;
    const int wn   = wid & 3;

    #pragma unroll
    for (int i = 0; i < 4; i++)
        #pragma unroll
        for (int j = 0; j < 4; j++)
            #pragma unroll
            for (int e = 0; e < 4; e++) acc[i][j][e] = 0.f;

    const uint32_t a_off = (uint32_t)((wm * 64 + (lane & 15)) * SROW + (lane >> 4) * 16);
    const uint32_t b_off = (uint32_t)((wn * 32 + (lane >> 4) * 8 + (lane & 7)) * SROW
                                      + ((lane >> 3) & 1) * 16);

    #pragma unroll
    for (int s = 0; s < NST; s++) {
        uint32_t st = sb + s * STAGE_SM;
        ld_tile(Ah, rowA, s * BK, st + 0 * TILE_SM, tid);
        ld_tile(Al, rowA, s * BK, st + 1 * TILE_SM, tid);
        ld_tile(Wh, rowB, s * BK, st + 2 * TILE_SM, tid);
        ld_tile(Wl, rowB, s * BK, st + 3 * TILE_SM, tid);
        cp_commit_group();
    }

    for (int c = 0; c < NCHUNK; c++) {
        cp_wait_group<NST - 1>();
        __syncthreads();

        const uint32_t st = sb + (c % NST) * STAGE_SM;
        #pragma unroll
        for (int ks = 0; ks < 2; ks++) {
            const uint32_t kb = ks * 32;
            uint32_t bh[8], bl[8];
            ldsm4(bh,     st + 2 * TILE_SM + b_off + kb);
            ldsm4(bh + 4, st + 2 * TILE_SM + b_off + kb + 16 * SROW);
            ldsm4(bl,     st + 3 * TILE_SM + b_off + kb);
            ldsm4(bl + 4, st + 3 * TILE_SM + b_off + kb + 16 * SROW);
            #pragma unroll
            for (int mf = 0; mf < 4; mf++) {
                uint32_t ah[4], al[4];
                ldsm4(ah, st + 0 * TILE_SM + a_off + kb + mf * 16 * SROW);
                ldsm4(al, st + 1 * TILE_SM + a_off + kb + mf * 16 * SROW);
                #pragma unroll
                for (int nf = 0; nf < 4; nf++) {
                    mma16816(acc[mf][nf], ah, bh + nf * 2);
                    mma16816(acc[mf][nf], ah, bl + nf * 2);
                    mma16816(acc[mf][nf], al, bh + nf * 2);
                }
            }
        }
        __syncthreads();

        if (c + NST < NCHUNK) {
            int k0 = (c + NST) * BK;
            ld_tile(Ah, rowA, k0, st + 0 * TILE_SM, tid);
            ld_tile(Al, rowA, k0, st + 1 * TILE_SM, tid);
            ld_tile(Wh, rowB, k0, st + 2 * TILE_SM, tid);
            ld_tile(Wl, rowB, k0, st + 3 * TILE_SM, tid);
        }
        cp_commit_group();
    }
}

// QKV projection: epilogue writes bf16 hi/lo directly (Q pre-scaled by 1/8)
__global__ void __launch_bounds__(256, 1)
gemm_qkv_tc() {
    const int w = blockIdx.z;
    __nv_bfloat16* H = (w == 0) ? g_qh : (w == 1) ? g_kh : g_vh;
    __nv_bfloat16* L = (w == 0) ? g_ql : (w == 1) ? g_kl : g_vl;
    const float scale = (w == 0) ? 0.125f : 1.0f;

    const int rowA = blockIdx.y * BM;
    const int rowB = blockIdx.x * BN;
    float acc[4][4][4];
    gemm_core(g_xh, g_xl, g_wh[w], g_wl[w], rowA, rowB, acc);

    const int lane = threadIdx.x & 31;
    const int wid  = threadIdx.x >> 5;
    const int wm   = wid >> 2, wn = wid & 3;
    const int r0c  = lane >> 2;
    const int cc   = (lane & 3) * 2;
    #pragma unroll
    for (int mf = 0; mf < 4; mf++) {
        const int mrow = rowA + wm * 64 + mf * 16;
        #pragma unroll
        for (int nf = 0; nf < 4; nf++) {
            const int col = rowB + wn * 32 + nf * 8 + cc;
            #pragma unroll
            for (int half = 0; half < 2; half++) {
                float v0 = acc[mf][nf][half * 2 + 0] * scale;
                float v1 = acc[mf][nf][half * 2 + 1] * scale;
                __nv_bfloat16 h0 = __float2bfloat16(v0);
                __nv_bfloat16 h1 = __float2bfloat16(v1);
                float l0 = v0 - __bfloat162float(h0);
                float l1 = v1 - __bfloat162float(h1);
                size_t idx = (size_t)(mrow + r0c + half * 8) * DMODEL + col;
                *(__nv_bfloat162*)(H + idx) = __halves2bfloat162(h0, h1);
                *(__nv_bfloat162*)(L + idx) = __halves2bfloat162(__float2bfloat16(l0),
                                                                 __float2bfloat16(l1));
            }
        }
    }
}

// output projection: fp32 epilogue to d_out
__global__ void __launch_bounds__(256, 1)
gemm_out_tc(float* __restrict__ out) {
    const int rowA = blockIdx.y * BM;
    const int rowB = blockIdx.x * BN;
    float acc[4][4][4];
    gemm_core(g_ch, g_cl, g_wh[3], g_wl[3], rowA, rowB, acc);

    const int lane = threadIdx.x & 31;
    const int wid  = threadIdx.x >> 5;
    const int wm   = wid >> 2, wn = wid & 3;
    const int r0c  = lane >> 2;
    const int cc   = (lane & 3) * 2;
    #pragma unroll
    for (int mf = 0; mf < 4; mf++) {
        const int mrow = rowA + wm * 64 + mf * 16;
        #pragma unroll
        for (int nf = 0; nf < 4; nf++) {
            const int col = rowB + wn * 32 + nf * 8 + cc;
            *(float2*)(out + (size_t)(mrow + r0c) * DMODEL + col) =
                make_float2(acc[mf][nf][0], acc[mf][nf][1]);
            *(float2*)(out + (size_t)(mrow + r0c + 8) * DMODEL + col) =
                make_float2(acc[mf][nf][2], acc[mf][nf][3]);
        }
    }
}

// ================= fp32 -> bf16 hi/lo split (x and weights only) ===============
__global__ void __launch_bounds__(256)
split_kernel(const float* __restrict__ in, __nv_bfloat16* __restrict__ hi,
             __nv_bfloat16* __restrict__ lo, int n4) {
    __nv_bfloat162* H = (__nv_bfloat162*)hi;
    __nv_bfloat162* L = (__nv_bfloat162*)lo;
    for (int i = blockIdx.x * blockDim.x + threadIdx.x; i < n4;
         i += gridDim.x * blockDim.x) {
        float4 v = ((const float4*)in)[i];
        float a[4] = {v.x, v.y, v.z, v.w};
        __nv_bfloat16 h[4], l[4];
        #pragma unroll
        for (int j = 0; j < 4; j++) {
            h[j] = __float2bfloat16(a[j]);
            l[j] = __float2bfloat16(a[j] - __bfloat162float(h[j]));
        }
        H[2 * i]     = __halves2bfloat162(h[0], h[1]);
        H[2 * i + 1] = __halves2bfloat162(h[2], h[3]);
        L[2 * i]     = __halves2bfloat162(l[0], l[1]);
        L[2 * i + 1] = __halves2bfloat162(l[2], l[3]);
    }
}

// ================= Flash attention via mma.sync (causal) =======================
// CTA: 64 q-rows x full head. 4 warps, warp w owns rows 16w..16w+15.
// S = QhKh + QhKl + QlKh ; P split Ph/Pl ; O += PhVh + PhVl + PlVh.
#define ASROW 144                       // 64 bf16 = 128B + 16 pad (16B aligned)
#define AQTILE (64 * ASROW)             // 9216 B
#define ASTAGE (4 * AQTILE)             // Kh,Kl,Vh,Vl = 36864 B
#define ATTN_SMEM2 (2 * AQTILE + 2 * ASTAGE)   // 92160 B

__device__ __forceinline__ void attn_ld_tile(const __nv_bfloat16* __restrict__ g,
                                             size_t growbase, int colbase,
                                             uint32_t dst, int tid) {
    #pragma unroll
    for (int l = 0; l < 4; l++) {
        int f = tid + (l << 7);          // 0..511
        int r = f >> 3;                  // row 0..63
        int u = f & 7;                   // 16B unit
        cp_async16(dst + r * ASROW + u * 16,
                   g + (growbase + r) * DMODEL + colbase + u * 8);
    }
}

__global__ void __launch_bounds__(128)
attn_mma_kernel() {
    extern __shared__ __align__(128) char asmem[];
    const uint32_t sb = smem_u32(asmem);
    const uint32_t QH = sb, QL = sb + AQTILE;
    const uint32_t ST0 = sb + 2 * AQTILE;

    const int tid  = threadIdx.x;
    const int w    = tid >> 5;
    const int lane = tid & 31;
    const int qb   = blockIdx.x;         // 0..31
    const int bh   = blockIdx.y;
    const int b    = bh >> 4;
    const int h    = bh & 15;

    const size_t qrow = (size_t)b * SEQ + qb * 64;
    const int    hcol = h * DK;

    // load Q tiles
    attn_ld_tile(g_qh, qrow, hcol, QH, tid);
    attn_ld_tile(g_ql, qrow, hcol, QL, tid);
    cp_commit_group();
    // load KV stage 0
    {
        size_t krow = (size_t)b * SEQ;
        attn_ld_tile(g_kh, krow, hcol, ST0 + 0 * AQTILE, tid);
        attn_ld_tile(g_kl, krow, hcol, ST0 + 1 * AQTILE, tid);
        attn_ld_tile(g_vh, krow, hcol, ST0 + 2 * AQTILE, tid);
        attn_ld_tile(g_vl, krow, hcol, ST0 + 3 * AQTILE, tid);
        cp_commit_group();
    }
    cp_wait_group<0>();
    __syncthreads();

    // Q fragments (persistent)
    const uint32_t a_off = (uint32_t)((w * 16 + (lane & 15)) * ASROW + (lane >> 4) * 16);
    uint32_t qh_a[4][4], ql_a[4][4];
    #pragma unroll
    for (int sk = 0; sk < 4; sk++) {
        ldsm4(qh_a[sk], QH + a_off + sk * 32);
        ldsm4(ql_a[sk], QL + a_off + sk * 32);
    }

    float o[8][4];
    #pragma unroll
    for (int f = 0; f < 8; f++)
        #pragma unroll
        for (int e = 0; e < 4; e++) o[f][e] = 0.f;
    float mA = -1e30f, mB = -1e30f, lA = 0.f, lB = 0.f;

    const uint32_t kb_off = (uint32_t)(((lane >> 4) * 8 + (lane & 7)) * ASROW
                                       + ((lane >> 3) & 1) * 16);
    const uint32_t vt_off = (uint32_t)(((lane & 7) + 8 * ((lane >> 3) & 1)) * ASROW
                                       + (lane >> 4) * 16);

    for (int kb = 0; kb <= qb; kb++) {
        __syncthreads();   // all warps done with stage (kb+1)&1 from iteration kb-1
        if (kb + 1 <= qb) {
            uint32_t st = ST0 + ((kb + 1) & 1) * ASTAGE;
            size_t krow = (size_t)b * SEQ + (kb + 1) * 64;
            attn_ld_tile(g_kh, krow, hcol, st + 0 * AQTILE, tid);
            attn_ld_tile(g_kl, krow, hcol, st + 1 * AQTILE, tid);
            attn_ld_tile(g_vh, krow, hcol, st + 2 * AQTILE, tid);
            attn_ld_tile(g_vl, krow, hcol, st + 3 * AQTILE, tid);
        }
        cp_commit_group();
        cp_wait_group<1>();   // KV(kb) resident
        __syncthreads();

        const uint32_t st = ST0 + (kb & 1) * ASTAGE;
        const uint32_t KH = st, KL = st + AQTILE, VH = st + 2 * AQTILE, VL = st + 3 * AQTILE;

        // ---- S = Q K^T (3 split passes), fp32 frags s[8][4] ----
        float s[8][4];
        #pragma unroll
        for (int f = 0; f < 8; f++)
            #pragma unroll
            for (int e = 0; e < 4; e++) s[f][e] = 0.f;

        #pragma unroll
        for (int sk = 0; sk < 4; sk++) {
            #pragma unroll
            for (int np = 0; np < 4; np++) {
                uint32_t bh4[4], bl4[4];
                uint32_t base = np * 16 * ASROW + kb_off + sk * 32;
                ldsm4(bh4, KH + base);
                ldsm4(bl4, KL + base);
                #pragma unroll
                for (int half = 0; half < 2; half++) {
                    const int nf = np * 2 + half;
                    mma16816(s[nf], qh_a[sk], bh4 + half * 2);
                    mma16816(s[nf], qh_a[sk], bl4 + half * 2);
                    mma16816(s[nf], ql_a[sk], bh4 + half * 2);
                }
            }
        }

        // ---- causal mask on diagonal tile ----
        if (kb == qb) {
            const int rA = w * 16 + (lane >> 2);
            const int rB = rA + 8;
            #pragma unroll
            for (int f = 0; f < 8; f++) {
                const int c0 = f * 8 + (lane & 3) * 2;
                if (c0 > rA)     s[f][0] = -1e30f;
                if (c0 + 1 > rA) s[f][1] = -1e30f;
                if (c0 > rB)     s[f][2] = -1e30f;
                if (c0 + 1 > rB) s[f][3] = -1e30f;
            }
        }

        // ---- online softmax (rows spread over quad lanes) ----
        float mAn = mA, mBn = mB;
        #pragma unroll
        for (int f = 0; f < 8; f++) {
            mAn = fmaxf(mAn, fmaxf(s[f][0], s[f][1]));
            mBn = fmaxf(mBn, fmaxf(s[f][2], s[f][3]));
        }
        mAn = fmaxf(mAn, __shfl_xor_sync(0xffffffffu, mAn, 1));
        mAn = fmaxf(mAn, __shfl_xor_sync(0xffffffffu, mAn, 2));
        mBn = fmaxf(mBn, __shfl_xor_sync(0xffffffffu, mBn, 1));
        mBn = fmaxf(mBn, __shfl_xor_sync(0xffffffffu, mBn, 2));

        const float alA = __expf(mA - mAn);
        const float alB = __expf(mB - mBn);
        float sumA = 0.f, sumB = 0.f;
        #pragma unroll
        for (int f = 0; f < 8; f++) {
            s[f][0] = __expf(s[f][0] - mAn);
            s[f][1] = __expf(s[f][1] - mAn);
            s[f][2] = __expf(s[f][2] - mBn);
            s[f][3] = __expf(s[f][3] - mBn);
            sumA += s[f][0] + s[f][1];
            sumB += s[f][2] + s[f][3];
        }
        sumA += __shfl_xor_sync(0xffffffffu, sumA, 1);
        sumA += __shfl_xor_sync(0xffffffffu, sumA, 2);
        sumB += __shfl_xor_sync(0xffffffffu, sumB, 1);
        sumB += __shfl_xor_sync(0xffffffffu, sumB, 2);
        lA = lA * alA + sumA;
        lB = lB * alB + sumB;
        mA = mAn; mB = mBn;

        #pragma unroll
        for (int f = 0; f < 8; f++) {
            o[f][0] *= alA; o[f][1] *= alA;
            o[f][2] *= alB; o[f][3] *= alB;
        }

        // ---- O += P V (3 split passes); P a-frags from S c-frags ----
        #pragma unroll
        for (int t = 0; t < 4; t++) {
            const int f0 = 2 * t, f1 = 2 * t + 1;
            uint32_t ah[4], al[4];
            // hi parts
            ah[0] = pack_bf16x2(s[f0][0], s[f0][1]);
            ah[1] = pack_bf16x2(s[f0][2], s[f0][3]);
            ah[2] = pack_bf16x2(s[f1][0], s[f1][1]);
            ah[3] = pack_bf16x2(s[f1][2], s[f1][3]);
            // residuals
            {
                float r00 = s[f0][0] - __bfloat162float(__float2bfloat16(s[f0][0]));
                float r01 = s[f0][1] - __bfloat162float(__float2bfloat16(s[f0][1]));
                float r02 = s[f0][2] - __bfloat162float(__float2bfloat16(s[f0][2]));
                float r03 = s[f0][3] - __bfloat162float(__float2bfloat16(s[f0][3]));
                float r10 = s[f1][0] - __bfloat162float(__float2bfloat16(s[f1][0]));
                float r11 = s[f1][1] - __bfloat162float(__float2bfloat16(s[f1][1]));
                float r12 = s[f1][2] - __bfloat162float(__float2bfloat16(s[f1][2]));
                float r13 = s[f1][3] - __bfloat162float(__float2bfloat16(s[f1][3]));
                al[0] = pack_bf16x2(r00, r01);
                al[1] = pack_bf16x2(r02, r03);
                al[2] = pack_bf16x2(r10, r11);
                al[3] = pack_bf16x2(r12, r13);
            }
            #pragma unroll
            for (int u = 0; u < 4; u++) {
                uint32_t vh4[4], vl4[4];
                uint32_t base = (t * 16) * ASROW + u * 32 + vt_off;
                ldsm4t(vh4, VH + base);
                ldsm4t(vl4, VL + base);
                mma16816(o[2 * u],     ah, vh4);
                mma16816(o[2 * u],     ah, vl4);
                mma16816(o[2 * u],     al, vh4);
                mma16816(o[2 * u + 1], ah, vh4 + 2);
                mma16816(o[2 * u + 1], ah, vl4 + 2);
                mma16816(o[2 * u + 1], al, vh4 + 2);
            }
        }
    }

    // ---- epilogue: normalize + write ctx as bf16 hi/lo ----
    const float invA = 1.f / fmaxf(lA, 1e-9f);
    const float invB = 1.f / fmaxf(lB, 1e-9f);
    const size_t rowA = qrow + w * 16 + (lane >> 2);
    const size_t rowB = rowA + 8;
    #pragma unroll
    for (int f = 0; f < 8; f++) {
        const int col = hcol + f * 8 + (lane & 3) * 2;
        float vA0 = o[f][0] * invA, vA1 = o[f][1] * invA;
        float vB0 = o[f][2] * invB, vB1 = o[f][3] * invB;
        __nv_bfloat16 hA0 = __float2bfloat16(vA0), hA1 = __float2bfloat16(vA1);
        __nv_bfloat16 hB0 = __float2bfloat16(vB0), hB1 = __float2bfloat16(vB1);
        *(__nv_bfloat162*)(g_ch + rowA * DMODEL + col) = __halves2bfloat162(hA0, hA1);
        *(__nv_bfloat162*)(g_ch + rowB * DMODEL + col) = __halves2bfloat162(hB0, hB1);
        *(__nv_bfloat162*)(g_cl + rowA * DMODEL + col) =
            __halves2bfloat162(__float2bfloat16(vA0 - __bfloat162float(hA0)),
                               __float2bfloat16(vA1 - __bfloat162float(hA1)));
        *(__nv_bfloat162*)(g_cl + rowB * DMODEL + col) =
            __halves2bfloat162(__float2bfloat16(vB0 - __bfloat162float(hB0)),
                               __float2bfloat16(vB1 - __bfloat162float(hB1)));
    }
}

// ================= launch ======================================================
extern "C" void kernel_launch(void* const* d_in, const int* in_sizes, int n_in,
                              void* d_out, int out_size)
{
    (void)in_sizes; (void)n_in; (void)out_size;
    const float* x  = (const float*)d_in[0];
    const float* wq = (const float*)d_in[1];
    const float* wk = (const float*)d_in[2];
    const float* wv = (const float*)d_in[3];
    const float* wo = (const float*)d_in[4];
    float* out = (float*)d_out;

    static cudaError_t a1 = cudaFuncSetAttribute(
        attn_mma_kernel, cudaFuncAttributeMaxDynamicSharedMemorySize, ATTN_SMEM2);
    static cudaError_t a2 = cudaFuncSetAttribute(
        gemm_qkv_tc, cudaFuncAttributeMaxDynamicSharedMemorySize, GEMM_SMEM);
    static cudaError_t a3 = cudaFuncSetAttribute(
        gemm_out_tc, cudaFuncAttributeMaxDynamicSharedMemorySize, GEMM_SMEM);
    (void)a1; (void)a2; (void)a3;

    __nv_bfloat16 *xh, *xl, *wh, *wl;
    cudaGetSymbolAddress((void**)&xh, g_xh);
    cudaGetSymbolAddress((void**)&xl, g_xl);
    cudaGetSymbolAddress((void**)&wh, g_wh);
    cudaGetSymbolAddress((void**)&wl, g_wl);

    const int NX = MROWS * DMODEL / 4;
    const int NW = DMODEL * DMODEL / 4;

    split_kernel<<<2048, 256>>>(x, xh, xl, NX);
    split_kernel<<<512, 256>>>(wq, wh + 0 * (size_t)DMODEL * DMODEL, wl + 0 * (size_t)DMODEL * DMODEL, NW);
    split_kernel<<<512, 256>>>(wk, wh + 1 * (size_t)DMODEL * DMODEL, wl + 1 * (size_t)DMODEL * DMODEL, NW);
    split_kernel<<<512, 256>>>(wv, wh + 2 * (size_t)DMODEL * DMODEL, wl + 2 * (size_t)DMODEL * DMODEL, NW);
    split_kernel<<<512, 256>>>(wo, wh + 3 * (size_t)DMODEL * DMODEL, wl + 3 * (size_t)DMODEL * DMODEL, NW);

    dim3 gqkv(DMODEL / BN, MROWS / BM, 3);
    gemm_qkv_tc<<<gqkv, 256, GEMM_SMEM>>>();

    dim3 gattn(SEQ / 64, BATCH * NHEAD);
    attn_mma_kernel<<<gattn, 128, ATTN_SMEM2>>>();

    dim3 gout(DMODEL / BN, MROWS / BM);
    gemm_out_tc<<<gout, 256, GEMM_SMEM>>>(out);
}

// round 5
// speedup vs baseline: 2.6687x; 1.5472x over previous
#include <cuda_runtime.h>
#include <cuda_bf16.h>
#include <cstdint>
#include <math.h>

#define BATCH  4
#define SEQ    2048
#define DMODEL 1024
#define NHEAD  16
#define DK     64
#define MROWS  (BATCH*SEQ)   // 8192

// ---------------- scratch (device globals: allocation-free rule) ----------------
__device__ __nv_bfloat16 g_xh[(size_t)MROWS * DMODEL];
__device__ __nv_bfloat16 g_xl[(size_t)MROWS * DMODEL];
__device__ __nv_bfloat16 g_qh[(size_t)MROWS * DMODEL];
__device__ __nv_bfloat16 g_ql[(size_t)MROWS * DMODEL];
__device__ __nv_bfloat16 g_kh[(size_t)MROWS * DMODEL];
__device__ __nv_bfloat16 g_kl[(size_t)MROWS * DMODEL];
__device__ __nv_bfloat16 g_vh[(size_t)MROWS * DMODEL];
__device__ __nv_bfloat16 g_vl[(size_t)MROWS * DMODEL];
__device__ __nv_bfloat16 g_ch[(size_t)MROWS * DMODEL];
__device__ __nv_bfloat16 g_cl[(size_t)MROWS * DMODEL];
__device__ __nv_bfloat16 g_wh[4][(size_t)DMODEL * DMODEL];
__device__ __nv_bfloat16 g_wl[4][(size_t)DMODEL * DMODEL];

// ================= PTX helpers (portable sm_80-class only) =====================
__device__ __forceinline__ uint32_t smem_u32(const void* p) {
    uint32_t a;
    asm("{ .reg .u64 t; cvta.to.shared.u64 t, %1; cvt.u32.u64 %0, t; }" : "=r"(a) : "l"(p));
    return a;
}
template <int N> __device__ __forceinline__ void cp_wait_group() {
    asm volatile("cp.async.wait_group %0;" :: "n"(N) : "memory");
}
__device__ __forceinline__ void cp_commit_group() {
    asm volatile("cp.async.commit_group;" ::: "memory");
}
__device__ __forceinline__ void cp_async16(uint32_t dst, const void* src) {
    asm volatile("cp.async.cg.shared.global [%0], [%1], 16;" :: "r"(dst), "l"(src) : "memory");
}
__device__ __forceinline__ void ldsm4(uint32_t* r, uint32_t addr) {
    asm volatile("ldmatrix.sync.aligned.m8n8.x4.shared.b16 {%0,%1,%2,%3}, [%4];"
                 : "=r"(r[0]), "=r"(r[1]), "=r"(r[2]), "=r"(r[3]) : "r"(addr));
}
__device__ __forceinline__ void ldsm4t(uint32_t* r, uint32_t addr) {
    asm volatile("ldmatrix.sync.aligned.m8n8.x4.trans.shared.b16 {%0,%1,%2,%3}, [%4];"
                 : "=r"(r[0]), "=r"(r[1]), "=r"(r[2]), "=r"(r[3]) : "r"(addr));
}
__device__ __forceinline__ void mma16816(float* c, const uint32_t* a, const uint32_t* b) {
    asm volatile(
        "mma.sync.aligned.m16n8k16.row.col.f32.bf16.bf16.f32 "
        "{%0,%1,%2,%3}, {%4,%5,%6,%7}, {%8,%9}, {%0,%1,%2,%3};"
        : "+f"(c[0]), "+f"(c[1]), "+f"(c[2]), "+f"(c[3])
        : "r"(a[0]), "r"(a[1]), "r"(a[2]), "r"(a[3]), "r"(b[0]), "r"(b[1]));
}
__device__ __forceinline__ uint32_t pack_bf16x2(float lo, float hi) {
    __nv_bfloat162 t = __halves2bfloat162(__float2bfloat16(lo), __float2bfloat16(hi));
    return *(uint32_t*)&t;
}

// ================= bf16-split GEMM-NT via mma.sync =============================
#define BM 128
#define BN 128
#define BK 32
#define NST 3
#define NCHUNK (DMODEL / BK)        // 32
#define SROW 80
#define TILE_SM (128 * SROW)
#define STAGE_SM (4 * TILE_SM)
#define GEMM_SMEM (NST * STAGE_SM)   // 122880

__device__ __forceinline__ void ld_tile(const __nv_bfloat16* __restrict__ g,
                                        int rowbase, int k0, uint32_t dst, int tid) {
    #pragma unroll
    for (int l = 0; l < 2; l++) {
        int f = tid + (l << 8);
        int r = f >> 2;
        int c = f & 3;
        const __nv_bfloat16* src = g + (size_t)(rowbase + r) * DMODEL + k0 + c * 8;
        cp_async16(dst + r * SROW + c * 16, src);
    }
}

__device__ __forceinline__ void gemm_core(const __nv_bfloat16* __restrict__ Ah,
                                          const __nv_bfloat16* __restrict__ Al,
                                          const __nv_bfloat16* __restrict__ Wh,
                                          const __nv_bfloat16* __restrict__ Wl,
                                          int rowA, int rowB,
                                          float acc[4][4][4]) {
    extern __shared__ __align__(128) char smem[];
    const uint32_t sb = smem_u32(smem);
    const int tid  = threadIdx.x;
    const int wid  = tid >> 5;
    const int lane = tid & 31;
    const int wm   = wid >> 2;
    const int wn   = wid & 3;

    #pragma unroll
    for (int i = 0; i < 4; i++)
        #pragma unroll
        for (int j = 0; j < 4; j++)
            #pragma unroll
            for (int e = 0; e < 4; e++) acc[i][j][e] = 0.f;

    const uint32_t a_off = (uint32_t)((wm * 64 + (lane & 15)) * SROW + (lane >> 4) * 16);
    const uint32_t b_off = (uint32_t)((wn * 32 + (lane >> 4) * 8 + (lane & 7)) * SROW
                                      + ((lane >> 3) & 1) * 16);

    #pragma unroll
    for (int s = 0; s < NST; s++) {
        uint32_t st = sb + s * STAGE_SM;
        ld_tile(Ah, rowA, s * BK, st + 0 * TILE_SM, tid);
        ld_tile(Al, rowA, s * BK, st + 1 * TILE_SM, tid);
        ld_tile(Wh, rowB, s * BK, st + 2 * TILE_SM, tid);
        ld_tile(Wl, rowB, s * BK, st + 3 * TILE_SM, tid);
        cp_commit_group();
    }

    for (int c = 0; c < NCHUNK; c++) {
        cp_wait_group<NST - 1>();
        __syncthreads();

        const uint32_t st = sb + (c % NST) * STAGE_SM;
        #pragma unroll
        for (int ks = 0; ks < 2; ks++) {
            const uint32_t kb = ks * 32;
            uint32_t bh[8], bl[8];
            ldsm4(bh,     st + 2 * TILE_SM + b_off + kb);
            ldsm4(bh + 4, st + 2 * TILE_SM + b_off + kb + 16 * SROW);
            ldsm4(bl,     st + 3 * TILE_SM + b_off + kb);
            ldsm4(bl + 4, st + 3 * TILE_SM + b_off + kb + 16 * SROW);
            #pragma unroll
            for (int mf = 0; mf < 4; mf++) {
                uint32_t ah[4], al[4];
                ldsm4(ah, st + 0 * TILE_SM + a_off + kb + mf * 16 * SROW);
                ldsm4(al, st + 1 * TILE_SM + a_off + kb + mf * 16 * SROW);
                #pragma unroll
                for (int nf = 0; nf < 4; nf++) {
                    mma16816(acc[mf][nf], ah, bh + nf * 2);
                    mma16816(acc[mf][nf], ah, bl + nf * 2);
                    mma16816(acc[mf][nf], al, bh + nf * 2);
                }
            }
        }
        __syncthreads();

        if (c + NST < NCHUNK) {
            int k0 = (c + NST) * BK;
            ld_tile(Ah, rowA, k0, st + 0 * TILE_SM, tid);
            ld_tile(Al, rowA, k0, st + 1 * TILE_SM, tid);
            ld_tile(Wh, rowB, k0, st + 2 * TILE_SM, tid);
            ld_tile(Wl, rowB, k0, st + 3 * TILE_SM, tid);
        }
        cp_commit_group();
    }
}

__global__ void __launch_bounds__(256, 1)
gemm_qkv_tc() {
    const int w = blockIdx.z;
    __nv_bfloat16* H = (w == 0) ? g_qh : (w == 1) ? g_kh : g_vh;
    __nv_bfloat16* L = (w == 0) ? g_ql : (w == 1) ? g_kl : g_vl;
    const float scale = (w == 0) ? 0.125f : 1.0f;

    const int rowA = blockIdx.y * BM;
    const int rowB = blockIdx.x * BN;
    float acc[4][4][4];
    gemm_core(g_xh, g_xl, g_wh[w], g_wl[w], rowA, rowB, acc);

    const int lane = threadIdx.x & 31;
    const int wid  = threadIdx.x >> 5;
    const int wm   = wid >> 2, wn = wid & 3;
    const int r0c  = lane >> 2;
    const int cc   = (lane & 3) * 2;
    #pragma unroll
    for (int mf = 0; mf < 4; mf++) {
        const int mrow = rowA + wm * 64 + mf * 16;
        #pragma unroll
        for (int nf = 0; nf < 4; nf++) {
            const int col = rowB + wn * 32 + nf * 8 + cc;
            #pragma unroll
            for (int half = 0; half < 2; half++) {
                float v0 = acc[mf][nf][half * 2 + 0] * scale;
                float v1 = acc[mf][nf][half * 2 + 1] * scale;
                __nv_bfloat16 h0 = __float2bfloat16(v0);
                __nv_bfloat16 h1 = __float2bfloat16(v1);
                float l0 = v0 - __bfloat162float(h0);
                float l1 = v1 - __bfloat162float(h1);
                size_t idx = (size_t)(mrow + r0c + half * 8) * DMODEL + col;
                *(__nv_bfloat162*)(H + idx) = __halves2bfloat162(h0, h1);
                *(__nv_bfloat162*)(L + idx) = __halves2bfloat162(__float2bfloat16(l0),
                                                                 __float2bfloat16(l1));
            }
        }
    }
}

__global__ void __launch_bounds__(256, 1)
gemm_out_tc(float* __restrict__ out) {
    const int rowA = blockIdx.y * BM;
    const int rowB = blockIdx.x * BN;
    float acc[4][4][4];
    gemm_core(g_ch, g_cl, g_wh[3], g_wl[3], rowA, rowB, acc);

    const int lane = threadIdx.x & 31;
    const int wid  = threadIdx.x >> 5;
    const int wm   = wid >> 2, wn = wid & 3;
    const int r0c  = lane >> 2;
    const int cc   = (lane & 3) * 2;
    #pragma unroll
    for (int mf = 0; mf < 4; mf++) {
        const int mrow = rowA + wm * 64 + mf * 16;
        #pragma unroll
        for (int nf = 0; nf < 4; nf++) {
            const int col = rowB + wn * 32 + nf * 8 + cc;
            *(float2*)(out + (size_t)(mrow + r0c) * DMODEL + col) =
                make_float2(acc[mf][nf][0], acc[mf][nf][1]);
            *(float2*)(out + (size_t)(mrow + r0c + 8) * DMODEL + col) =
                make_float2(acc[mf][nf][2], acc[mf][nf][3]);
        }
    }
}

// ================= fp32 -> bf16 hi/lo splits ===================================
__global__ void __launch_bounds__(256)
split_kernel(const float* __restrict__ in, __nv_bfloat16* __restrict__ hi,
             __nv_bfloat16* __restrict__ lo, int n4) {
    __nv_bfloat162* H = (__nv_bfloat162*)hi;
    __nv_bfloat162* L = (__nv_bfloat162*)lo;
    for (int i = blockIdx.x * blockDim.x + threadIdx.x; i < n4;
         i += gridDim.x * blockDim.x) {
        float4 v = ((const float4*)in)[i];
        float a[4] = {v.x, v.y, v.z, v.w};
        __nv_bfloat16 h[4], l[4];
        #pragma unroll
        for (int j = 0; j < 4; j++) {
            h[j] = __float2bfloat16(a[j]);
            l[j] = __float2bfloat16(a[j] - __bfloat162float(h[j]));
        }
        H[2 * i]     = __halves2bfloat162(h[0], h[1]);
        H[2 * i + 1] = __halves2bfloat162(h[2], h[3]);
        L[2 * i]     = __halves2bfloat162(l[0], l[1]);
        L[2 * i + 1] = __halves2bfloat162(l[2], l[3]);
    }
}

// two weights in one launch (z picks); shrinks launch count so attn is launch #5
__global__ void __launch_bounds__(256)
split2_kernel(const float* __restrict__ in0, const float* __restrict__ in1,
              __nv_bfloat16* __restrict__ hi0, __nv_bfloat16* __restrict__ lo0,
              __nv_bfloat16* __restrict__ hi1, __nv_bfloat16* __restrict__ lo1,
              int n4) {
    const float* in = blockIdx.z ? in1 : in0;
    __nv_bfloat162* H = (__nv_bfloat162*)(blockIdx.z ? hi1 : hi0);
    __nv_bfloat162* L = (__nv_bfloat162*)(blockIdx.z ? lo1 : lo0);
    for (int i = blockIdx.x * blockDim.x + threadIdx.x; i < n4;
         i += gridDim.x * blockDim.x) {
        float4 v = ((const float4*)in)[i];
        float a[4] = {v.x, v.y, v.z, v.w};
        __nv_bfloat16 h[4], l[4];
        #pragma unroll
        for (int j = 0; j < 4; j++) {
            h[j] = __float2bfloat16(a[j]);
            l[j] = __float2bfloat16(a[j] - __bfloat162float(h[j]));
        }
        H[2 * i]     = __halves2bfloat162(h[0], h[1]);
        H[2 * i + 1] = __halves2bfloat162(h[2], h[3]);
        L[2 * i]     = __halves2bfloat162(l[0], l[1]);
        L[2 * i + 1] = __halves2bfloat162(l[2], l[3]);
    }
}

// ================= Flash attention via mma.sync (causal) =======================
// CTA: 128 q-rows, 8 warps (16 rows each). K/V tiles 64 rows, double buffered.
#define AQROWS 128
#define ASROW  144
#define AQTILE (AQROWS * ASROW)         // 18432
#define AKTILE (64 * ASROW)             // 9216
#define ASTAGE (4 * AKTILE)             // 36864
#define ATTN_SMEM2 (2 * AQTILE + 2 * ASTAGE)   // 110592

__device__ __forceinline__ void attn_ld_q(const __nv_bfloat16* __restrict__ g,
                                          size_t growbase, int colbase,
                                          uint32_t dst, int tid) {
    #pragma unroll
    for (int l = 0; l < 4; l++) {
        int f = tid + (l << 8);          // 0..1023
        int r = f >> 3;                  // row 0..127
        int u = f & 7;
        cp_async16(dst + r * ASROW + u * 16,
                   g + (growbase + r) * DMODEL + colbase + u * 8);
    }
}
__device__ __forceinline__ void attn_ld_kv(const __nv_bfloat16* __restrict__ g,
                                           size_t growbase, int colbase,
                                           uint32_t dst, int tid) {
    #pragma unroll
    for (int l = 0; l < 2; l++) {
        int f = tid + (l << 8);          // 0..511
        int r = f >> 3;                  // row 0..63
        int u = f & 7;
        cp_async16(dst + r * ASROW + u * 16,
                   g + (growbase + r) * DMODEL + colbase + u * 8);
    }
}

__global__ void __launch_bounds__(256, 2)
attn_mma_kernel() {
    extern __shared__ __align__(128) char asmem[];
    const uint32_t sb = smem_u32(asmem);
    const uint32_t QH = sb, QL = sb + AQTILE;
    const uint32_t ST0 = sb + 2 * AQTILE;

    const int tid  = threadIdx.x;
    const int w    = tid >> 5;           // 0..7
    const int lane = tid & 31;
    const int qb   = (gridDim.x - 1) - blockIdx.x;   // longest CTAs first
    const int bh   = blockIdx.y;
    const int b    = bh >> 4;
    const int h    = bh & 15;

    const size_t qrow = (size_t)b * SEQ + qb * AQROWS;
    const int    hcol = h * DK;
    const int    kmax = 2 * qb + 1;

    attn_ld_q(g_qh, qrow, hcol, QH, tid);
    attn_ld_q(g_ql, qrow, hcol, QL, tid);
    cp_commit_group();
    {
        size_t krow = (size_t)b * SEQ;
        attn_ld_kv(g_kh, krow, hcol, ST0 + 0 * AKTILE, tid);
        attn_ld_kv(g_kl, krow, hcol, ST0 + 1 * AKTILE, tid);
        attn_ld_kv(g_vh, krow, hcol, ST0 + 2 * AKTILE, tid);
        attn_ld_kv(g_vl, krow, hcol, ST0 + 3 * AKTILE, tid);
        cp_commit_group();
    }
    cp_wait_group<0>();
    __syncthreads();

    const uint32_t a_off = (uint32_t)((w * 16 + (lane & 15)) * ASROW + (lane >> 4) * 16);
    uint32_t qh_a[4][4], ql_a[4][4];
    #pragma unroll
    for (int sk = 0; sk < 4; sk++) {
        ldsm4(qh_a[sk], QH + a_off + sk * 32);
        ldsm4(ql_a[sk], QL + a_off + sk * 32);
    }

    float o[8][4];
    #pragma unroll
    for (int f = 0; f < 8; f++)
        #pragma unroll
        for (int e = 0; e < 4; e++) o[f][e] = 0.f;
    float mA = -1e30f, mB = -1e30f, lA = 0.f, lB = 0.f;

    const uint32_t kb_off = (uint32_t)(((lane >> 4) * 8 + (lane & 7)) * ASROW
                                       + ((lane >> 3) & 1) * 16);
    const uint32_t vt_off = (uint32_t)(((lane & 7) + 8 * ((lane >> 3) & 1)) * ASROW
                                       + (lane >> 4) * 16);

    for (int kb = 0; kb <= kmax; kb++) {
        __syncthreads();
        if (kb + 1 <= kmax) {
            uint32_t st = ST0 + ((kb + 1) & 1) * ASTAGE;
            size_t krow = (size_t)b * SEQ + (size_t)(kb + 1) * 64;
            attn_ld_kv(g_kh, krow, hcol, st + 0 * AKTILE, tid);
            attn_ld_kv(g_kl, krow, hcol, st + 1 * AKTILE, tid);
            attn_ld_kv(g_vh, krow, hcol, st + 2 * AKTILE, tid);
            attn_ld_kv(g_vl, krow, hcol, st + 3 * AKTILE, tid);
        }
        cp_commit_group();
        cp_wait_group<1>();
        __syncthreads();

        const uint32_t st = ST0 + (kb & 1) * ASTAGE;
        const uint32_t KH = st, KL = st + AKTILE, VH = st + 2 * AKTILE, VL = st + 3 * AKTILE;

        // ---- S = Q K^T (3 split passes) ----
        float s[8][4];
        #pragma unroll
        for (int f = 0; f < 8; f++)
            #pragma unroll
            for (int e = 0; e < 4; e++) s[f][e] = 0.f;

        #pragma unroll
        for (int sk = 0; sk < 4; sk++) {
            #pragma unroll
            for (int np = 0; np < 4; np++) {
                uint32_t bh4[4], bl4[4];
                uint32_t base = np * 16 * ASROW + kb_off + sk * 32;
                ldsm4(bh4, KH + base);
                ldsm4(bl4, KL + base);
                #pragma unroll
                for (int half = 0; half < 2; half++) {
                    const int nf = np * 2 + half;
                    mma16816(s[nf], qh_a[sk], bh4 + half * 2);
                    mma16816(s[nf], qh_a[sk], bl4 + half * 2);
                    mma16816(s[nf], ql_a[sk], bh4 + half * 2);
                }
            }
        }

        // ---- causal mask (global row/col compare; active only near diagonal) ----
        if (kb >= 2 * qb) {
            const int rA = w * 16 + (lane >> 2);          // row within q-tile
            const int rB = rA + 8;
            const int cbase = kb * 64 - qb * AQROWS;      // col minus row base
            #pragma unroll
            for (int f = 0; f < 8; f++) {
                const int c0 = cbase + f * 8 + (lane & 3) * 2;
                if (c0 > rA)     s[f][0] = -1e30f;
                if (c0 + 1 > rA) s[f][1] = -1e30f;
                if (c0 > rB)     s[f][2] = -1e30f;
                if (c0 + 1 > rB) s[f][3] = -1e30f;
            }
        }

        // ---- online softmax ----
        float mAn = mA, mBn = mB;
        #pragma unroll
        for (int f = 0; f < 8; f++) {
            mAn = fmaxf(mAn, fmaxf(s[f][0], s[f][1]));
            mBn = fmaxf(mBn, fmaxf(s[f][2], s[f][3]));
        }
        mAn = fmaxf(mAn, __shfl_xor_sync(0xffffffffu, mAn, 1));
        mAn = fmaxf(mAn, __shfl_xor_sync(0xffffffffu, mAn, 2));
        mBn = fmaxf(mBn, __shfl_xor_sync(0xffffffffu, mBn, 1));
        mBn = fmaxf(mBn, __shfl_xor_sync(0xffffffffu, mBn, 2));

        const float alA = __expf(mA - mAn);
        const float alB = __expf(mB - mBn);
        float sumA = 0.f, sumB = 0.f;
        #pragma unroll
        for (int f = 0; f < 8; f++) {
            s[f][0] = __expf(s[f][0] - mAn);
            s[f][1] = __expf(s[f][1] - mAn);
            s[f][2] = __expf(s[f][2] - mBn);
            s[f][3] = __expf(s[f][3] - mBn);
            sumA += s[f][0] + s[f][1];
            sumB += s[f][2] + s[f][3];
        }
        sumA += __shfl_xor_sync(0xffffffffu, sumA, 1);
        sumA += __shfl_xor_sync(0xffffffffu, sumA, 2);
        sumB += __shfl_xor_sync(0xffffffffu, sumB, 1);
        sumB += __shfl_xor_sync(0xffffffffu, sumB, 2);
        lA = lA * alA + sumA;
        lB = lB * alB + sumB;
        mA = mAn; mB = mBn;

        #pragma unroll
        for (int f = 0; f < 8; f++) {
            o[f][0] *= alA; o[f][1] *= alA;
            o[f][2] *= alB; o[f][3] *= alB;
        }

        // ---- O += P V (3 split passes) ----
        #pragma unroll
        for (int t = 0; t < 4; t++) {
            const int f0 = 2 * t, f1 = 2 * t + 1;
            uint32_t ah[4], al[4];
            ah[0] = pack_bf16x2(s[f0][0], s[f0][1]);
            ah[1] = pack_bf16x2(s[f0][2], s[f0][3]);
            ah[2] = pack_bf16x2(s[f1][0], s[f1][1]);
            ah[3] = pack_bf16x2(s[f1][2], s[f1][3]);
            {
                float r00 = s[f0][0] - __bfloat162float(__float2bfloat16(s[f0][0]));
                float r01 = s[f0][1] - __bfloat162float(__float2bfloat16(s[f0][1]));
                float r02 = s[f0][2] - __bfloat162float(__float2bfloat16(s[f0][2]));
                float r03 = s[f0][3] - __bfloat162float(__float2bfloat16(s[f0][3]));
                float r10 = s[f1][0] - __bfloat162float(__float2bfloat16(s[f1][0]));
                float r11 = s[f1][1] - __bfloat162float(__float2bfloat16(s[f1][1]));
                float r12 = s[f1][2] - __bfloat162float(__float2bfloat16(s[f1][2]));
                float r13 = s[f1][3] - __bfloat162float(__float2bfloat16(s[f1][3]));
                al[0] = pack_bf16x2(r00, r01);
                al[1] = pack_bf16x2(r02, r03);
                al[2] = pack_bf16x2(r10, r11);
                al[3] = pack_bf16x2(r12, r13);
            }
            #pragma unroll
            for (int u = 0; u < 4; u++) {
                uint32_t vh4[4], vl4[4];
                uint32_t base = (t * 16) * ASROW + u * 32 + vt_off;
                ldsm4t(vh4, VH + base);
                ldsm4t(vl4, VL + base);
                mma16816(o[2 * u],     ah, vh4);
                mma16816(o[2 * u],     ah, vl4);
                mma16816(o[2 * u],     al, vh4);
                mma16816(o[2 * u + 1], ah, vh4 + 2);
                mma16816(o[2 * u + 1], ah, vl4 + 2);
                mma16816(o[2 * u + 1], al, vh4 + 2);
            }
        }
    }

    // ---- epilogue: normalize + ctx hi/lo ----
    const float invA = 1.f / fmaxf(lA, 1e-9f);
    const float invB = 1.f / fmaxf(lB, 1e-9f);
    const size_t rowA = qrow + w * 16 + (lane >> 2);
    const size_t rowB = rowA + 8;
    #pragma unroll
    for (int f = 0; f < 8; f++) {
        const int col = hcol + f * 8 + (lane & 3) * 2;
        float vA0 = o[f][0] * invA, vA1 = o[f][1] * invA;
        float vB0 = o[f][2] * invB, vB1 = o[f][3] * invB;
        __nv_bfloat16 hA0 = __float2bfloat16(vA0), hA1 = __float2bfloat16(vA1);
        __nv_bfloat16 hB0 = __float2bfloat16(vB0), hB1 = __float2bfloat16(vB1);
        *(__nv_bfloat162*)(g_ch + rowA * DMODEL + col) = __halves2bfloat162(hA0, hA1);
        *(__nv_bfloat162*)(g_ch + rowB * DMODEL + col) = __halves2bfloat162(hB0, hB1);
        *(__nv_bfloat162*)(g_cl + rowA * DMODEL + col) =
            __halves2bfloat162(__float2bfloat16(vA0 - __bfloat162float(hA0)),
                               __float2bfloat16(vA1 - __bfloat162float(hA1)));
        *(__nv_bfloat162*)(g_cl + rowB * DMODEL + col) =
            __halves2bfloat162(__float2bfloat16(vB0 - __bfloat162float(hB0)),
                               __float2bfloat16(vB1 - __bfloat162float(hB1)));
    }
}

// ================= launch ======================================================
extern "C" void kernel_launch(void* const* d_in, const int* in_sizes, int n_in,
                              void* d_out, int out_size)
{
    (void)in_sizes; (void)n_in; (void)out_size;
    const float* x  = (const float*)d_in[0];
    const float* wq = (const float*)d_in[1];
    const float* wk = (const float*)d_in[2];
    const float* wv = (const float*)d_in[3];
    const float* wo = (const float*)d_in[4];
    float* out = (float*)d_out;

    static cudaError_t a1 = cudaFuncSetAttribute(
        attn_mma_kernel, cudaFuncAttributeMaxDynamicSharedMemorySize, ATTN_SMEM2);
    static cudaError_t a2 = cudaFuncSetAttribute(
        gemm_qkv_tc, cudaFuncAttributeMaxDynamicSharedMemorySize, GEMM_SMEM);
    static cudaError_t a3 = cudaFuncSetAttribute(
        gemm_out_tc, cudaFuncAttributeMaxDynamicSharedMemorySize, GEMM_SMEM);
    (void)a1; (void)a2; (void)a3;

    __nv_bfloat16 *xh, *xl, *wh, *wl;
    cudaGetSymbolAddress((void**)&xh, g_xh);
    cudaGetSymbolAddress((void**)&xl, g_xl);
    cudaGetSymbolAddress((void**)&wh, g_wh);
    cudaGetSymbolAddress((void**)&wl, g_wl);

    const int NX = MROWS * DMODEL / 4;
    const int NW = DMODEL * DMODEL / 4;
    const size_t WSZ = (size_t)DMODEL * DMODEL;

    // launch 1
    split_kernel<<<2048, 256>>>(x, xh, xl, NX);
    // launch 2: wq + wk
    split2_kernel<<<dim3(512, 1, 2), 256>>>(wq, wk,
        wh + 0 * WSZ, wl + 0 * WSZ, wh + 1 * WSZ, wl + 1 * WSZ, NW);
    // launch 3: wv + wo
    split2_kernel<<<dim3(512, 1, 2), 256>>>(wv, wo,
        wh + 2 * WSZ, wl + 2 * WSZ, wh + 3 * WSZ, wl + 3 * WSZ, NW);

    // launch 4
    dim3 gqkv(DMODEL / BN, MROWS / BM, 3);
    gemm_qkv_tc<<<gqkv, 256, GEMM_SMEM>>>();

    // launch 5 (profiled by ncu -s 5 -c 1)
    dim3 gattn(SEQ / AQROWS, BATCH * NHEAD);
    attn_mma_kernel<<<gattn, 256, ATTN_SMEM2>>>();

    // launch 6
    dim3 gout(DMODEL / BN, MROWS / BM);
    gemm_out_tc<<<gout, 256, GEMM_SMEM>>>(out);
}

// round 6
// speedup vs baseline: 2.9838x; 1.1181x over previous
#include <cuda_runtime.h>
#include <cuda_bf16.h>
#include <cstdint>
#include <math.h>

#define BATCH  4
#define SEQ    2048
#define DMODEL 1024
#define NHEAD  16
#define DK     64
#define MROWS  (BATCH*SEQ)   // 8192

// ---------------- scratch (device globals: allocation-free rule) ----------------
__device__ __nv_bfloat16 g_xh[(size_t)MROWS * DMODEL];
__device__ __nv_bfloat16 g_xl[(size_t)MROWS * DMODEL];
__device__ __nv_bfloat16 g_qh[(size_t)MROWS * DMODEL];
__device__ __nv_bfloat16 g_ql[(size_t)MROWS * DMODEL];
__device__ __nv_bfloat16 g_kh[(size_t)MROWS * DMODEL];
__device__ __nv_bfloat16 g_kl[(size_t)MROWS * DMODEL];
__device__ __nv_bfloat16 g_vh[(size_t)MROWS * DMODEL];
__device__ __nv_bfloat16 g_vl[(size_t)MROWS * DMODEL];
__device__ __nv_bfloat16 g_ch[(size_t)MROWS * DMODEL];
__device__ __nv_bfloat16 g_cl[(size_t)MROWS * DMODEL];
__device__ __nv_bfloat16 g_wh[4][(size_t)DMODEL * DMODEL];
__device__ __nv_bfloat16 g_wl[4][(size_t)DMODEL * DMODEL];

// ================= PTX helpers (portable sm_80-class only) =====================
__device__ __forceinline__ uint32_t smem_u32(const void* p) {
    uint32_t a;
    asm("{ .reg .u64 t; cvta.to.shared.u64 t, %1; cvt.u32.u64 %0, t; }" : "=r"(a) : "l"(p));
    return a;
}
template <int N> __device__ __forceinline__ void cp_wait_group() {
    asm volatile("cp.async.wait_group %0;" :: "n"(N) : "memory");
}
__device__ __forceinline__ void cp_commit_group() {
    asm volatile("cp.async.commit_group;" ::: "memory");
}
__device__ __forceinline__ void cp_async16(uint32_t dst, const void* src) {
    asm volatile("cp.async.cg.shared.global [%0], [%1], 16;" :: "r"(dst), "l"(src) : "memory");
}
__device__ __forceinline__ void ldsm4(uint32_t* r, uint32_t addr) {
    asm volatile("ldmatrix.sync.aligned.m8n8.x4.shared.b16 {%0,%1,%2,%3}, [%4];"
                 : "=r"(r[0]), "=r"(r[1]), "=r"(r[2]), "=r"(r[3]) : "r"(addr));
}
__device__ __forceinline__ void ldsm4t(uint32_t* r, uint32_t addr) {
    asm volatile("ldmatrix.sync.aligned.m8n8.x4.trans.shared.b16 {%0,%1,%2,%3}, [%4];"
                 : "=r"(r[0]), "=r"(r[1]), "=r"(r[2]), "=r"(r[3]) : "r"(addr));
}
__device__ __forceinline__ void mma16816(float* c, const uint32_t* a, const uint32_t* b) {
    asm volatile(
        "mma.sync.aligned.m16n8k16.row.col.f32.bf16.bf16.f32 "
        "{%0,%1,%2,%3}, {%4,%5,%6,%7}, {%8,%9}, {%0,%1,%2,%3};"
        : "+f"(c[0]), "+f"(c[1]), "+f"(c[2]), "+f"(c[3])
        : "r"(a[0]), "r"(a[1]), "r"(a[2]), "r"(a[3]), "r"(b[0]), "r"(b[1]));
}
__device__ __forceinline__ uint32_t pack_bf16x2(float lo, float hi) {
    __nv_bfloat162 t = __halves2bfloat162(__float2bfloat16(lo), __float2bfloat16(hi));
    return *(uint32_t*)&t;
}

// ================= bf16-split GEMM-NT via mma.sync =============================
#define BM 128
#define BN 128
#define BK 32
#define NST 2
#define NCHUNK (DMODEL / BK)        // 32
#define SROW 80
#define TILE_SM (128 * SROW)
#define STAGE_SM (4 * TILE_SM)
#define GEMM_SMEM (NST * STAGE_SM)   // 81920 -> 2 CTA/SM

__device__ __forceinline__ void ld_tile(const __nv_bfloat16* __restrict__ g,
                                        int rowbase, int k0, uint32_t dst, int tid) {
    #pragma unroll
    for (int l = 0; l < 2; l++) {
        int f = tid + (l << 8);
        int r = f >> 2;
        int c = f & 3;
        const __nv_bfloat16* src = g + (size_t)(rowbase + r) * DMODEL + k0 + c * 8;
        cp_async16(dst + r * SROW + c * 16, src);
    }
}

__device__ __forceinline__ void gemm_core(const __nv_bfloat16* __restrict__ Ah,
                                          const __nv_bfloat16* __restrict__ Al,
                                          const __nv_bfloat16* __restrict__ Wh,
                                          const __nv_bfloat16* __restrict__ Wl,
                                          int rowA, int rowB,
                                          float acc[4][4][4]) {
    extern __shared__ __align__(128) char smem[];
    const uint32_t sb = smem_u32(smem);
    const int tid  = threadIdx.x;
    const int wid  = tid >> 5;
    const int lane = tid & 31;
    const int wm   = wid >> 2;
    const int wn   = wid & 3;

    #pragma unroll
    for (int i = 0; i < 4; i++)
        #pragma unroll
        for (int j = 0; j < 4; j++)
            #pragma unroll
            for (int e = 0; e < 4; e++) acc[i][j][e] = 0.f;

    const uint32_t a_off = (uint32_t)((wm * 64 + (lane & 15)) * SROW + (lane >> 4) * 16);
    const uint32_t b_off = (uint32_t)((wn * 32 + (lane >> 4) * 8 + (lane & 7)) * SROW
                                      + ((lane >> 3) & 1) * 16);

    #pragma unroll
    for (int s = 0; s < NST; s++) {
        uint32_t st = sb + s * STAGE_SM;
        ld_tile(Ah, rowA, s * BK, st + 0 * TILE_SM, tid);
        ld_tile(Al, rowA, s * BK, st + 1 * TILE_SM, tid);
        ld_tile(Wh, rowB, s * BK, st + 2 * TILE_SM, tid);
        ld_tile(Wl, rowB, s * BK, st + 3 * TILE_SM, tid);
        cp_commit_group();
    }

    for (int c = 0; c < NCHUNK; c++) {
        cp_wait_group<NST - 1>();
        __syncthreads();

        const uint32_t st = sb + (c % NST) * STAGE_SM;
        #pragma unroll
        for (int ks = 0; ks < 2; ks++) {
            const uint32_t kb = ks * 32;
            uint32_t bh[8], bl[8];
            ldsm4(bh,     st + 2 * TILE_SM + b_off + kb);
            ldsm4(bh + 4, st + 2 * TILE_SM + b_off + kb + 16 * SROW);
            ldsm4(bl,     st + 3 * TILE_SM + b_off + kb);
            ldsm4(bl + 4, st + 3 * TILE_SM + b_off + kb + 16 * SROW);
            #pragma unroll
            for (int mf = 0; mf < 4; mf++) {
                uint32_t ah[4], al[4];
                ldsm4(ah, st + 0 * TILE_SM + a_off + kb + mf * 16 * SROW);
                ldsm4(al, st + 1 * TILE_SM + a_off + kb + mf * 16 * SROW);
                #pragma unroll
                for (int nf = 0; nf < 4; nf++) {
                    mma16816(acc[mf][nf], ah, bh + nf * 2);
                    mma16816(acc[mf][nf], ah, bl + nf * 2);
                    mma16816(acc[mf][nf], al, bh + nf * 2);
                }
            }
        }
        __syncthreads();

        if (c + NST < NCHUNK) {
            int k0 = (c + NST) * BK;
            ld_tile(Ah, rowA, k0, st + 0 * TILE_SM, tid);
            ld_tile(Al, rowA, k0, st + 1 * TILE_SM, tid);
            ld_tile(Wh, rowB, k0, st + 2 * TILE_SM, tid);
            ld_tile(Wl, rowB, k0, st + 3 * TILE_SM, tid);
        }
        cp_commit_group();
    }
}

__global__ void __launch_bounds__(256, 2)
gemm_qkv_tc() {
    const int w = blockIdx.z;
    __nv_bfloat16* H = (w == 0) ? g_qh : (w == 1) ? g_kh : g_vh;
    __nv_bfloat16* L = (w == 0) ? g_ql : (w == 1) ? g_kl : g_vl;
    const float scale = (w == 0) ? 0.125f : 1.0f;

    const int rowA = blockIdx.y * BM;
    const int rowB = blockIdx.x * BN;
    float acc[4][4][4];
    gemm_core(g_xh, g_xl, g_wh[w], g_wl[w], rowA, rowB, acc);

    const int lane = threadIdx.x & 31;
    const int wid  = threadIdx.x >> 5;
    const int wm   = wid >> 2, wn = wid & 3;
    const int r0c  = lane >> 2;
    const int cc   = (lane & 3) * 2;
    #pragma unroll
    for (int mf = 0; mf < 4; mf++) {
        const int mrow = rowA + wm * 64 + mf * 16;
        #pragma unroll
        for (int nf = 0; nf < 4; nf++) {
            const int col = rowB + wn * 32 + nf * 8 + cc;
            #pragma unroll
            for (int half = 0; half < 2; half++) {
                float v0 = acc[mf][nf][half * 2 + 0] * scale;
                float v1 = acc[mf][nf][half * 2 + 1] * scale;
                __nv_bfloat16 h0 = __float2bfloat16(v0);
                __nv_bfloat16 h1 = __float2bfloat16(v1);
                float l0 = v0 - __bfloat162float(h0);
                float l1 = v1 - __bfloat162float(h1);
                size_t idx = (size_t)(mrow + r0c + half * 8) * DMODEL + col;
                *(__nv_bfloat162*)(H + idx) = __halves2bfloat162(h0, h1);
                *(__nv_bfloat162*)(L + idx) = __halves2bfloat162(__float2bfloat16(l0),
                                                                 __float2bfloat16(l1));
            }
        }
    }
}

__global__ void __launch_bounds__(256, 2)
gemm_out_tc(float* __restrict__ out) {
    const int rowA = blockIdx.y * BM;
    const int rowB = blockIdx.x * BN;
    float acc[4][4][4];
    gemm_core(g_ch, g_cl, g_wh[3], g_wl[3], rowA, rowB, acc);

    const int lane = threadIdx.x & 31;
    const int wid  = threadIdx.x >> 5;
    const int wm   = wid >> 2, wn = wid & 3;
    const int r0c  = lane >> 2;
    const int cc   = (lane & 3) * 2;
    #pragma unroll
    for (int mf = 0; mf < 4; mf++) {
        const int mrow = rowA + wm * 64 + mf * 16;
        #pragma unroll
        for (int nf = 0; nf < 4; nf++) {
            const int col = rowB + wn * 32 + nf * 8 + cc;
            *(float2*)(out + (size_t)(mrow + r0c) * DMODEL + col) =
                make_float2(acc[mf][nf][0], acc[mf][nf][1]);
            *(float2*)(out + (size_t)(mrow + r0c + 8) * DMODEL + col) =
                make_float2(acc[mf][nf][2], acc[mf][nf][3]);
        }
    }
}

// ================= fp32 -> bf16 hi/lo splits ===================================
__global__ void __launch_bounds__(256)
split_kernel(const float* __restrict__ in, __nv_bfloat16* __restrict__ hi,
             __nv_bfloat16* __restrict__ lo, int n4) {
    __nv_bfloat162* H = (__nv_bfloat162*)hi;
    __nv_bfloat162* L = (__nv_bfloat162*)lo;
    for (int i = blockIdx.x * blockDim.x + threadIdx.x; i < n4;
         i += gridDim.x * blockDim.x) {
        float4 v = ((const float4*)in)[i];
        float a[4] = {v.x, v.y, v.z, v.w};
        __nv_bfloat16 h[4], l[4];
        #pragma unroll
        for (int j = 0; j < 4; j++) {
            h[j] = __float2bfloat16(a[j]);
            l[j] = __float2bfloat16(a[j] - __bfloat162float(h[j]));
        }
        H[2 * i]     = __halves2bfloat162(h[0], h[1]);
        H[2 * i + 1] = __halves2bfloat162(h[2], h[3]);
        L[2 * i]     = __halves2bfloat162(l[0], l[1]);
        L[2 * i + 1] = __halves2bfloat162(l[2], l[3]);
    }
}

__global__ void __launch_bounds__(256)
split2_kernel(const float* __restrict__ in0, const float* __restrict__ in1,
              __nv_bfloat16* __restrict__ hi0, __nv_bfloat16* __restrict__ lo0,
              __nv_bfloat16* __restrict__ hi1, __nv_bfloat16* __restrict__ lo1,
              int n4) {
    const float* in = blockIdx.z ? in1 : in0;
    __nv_bfloat162* H = (__nv_bfloat162*)(blockIdx.z ? hi1 : hi0);
    __nv_bfloat162* L = (__nv_bfloat162*)(blockIdx.z ? lo1 : lo0);
    for (int i = blockIdx.x * blockDim.x + threadIdx.x; i < n4;
         i += gridDim.x * blockDim.x) {
        float4 v = ((const float4*)in)[i];
        float a[4] = {v.x, v.y, v.z, v.w};
        __nv_bfloat16 h[4], l[4];
        #pragma unroll
        for (int j = 0; j < 4; j++) {
            h[j] = __float2bfloat16(a[j]);
            l[j] = __float2bfloat16(a[j] - __bfloat162float(h[j]));
        }
        H[2 * i]     = __halves2bfloat162(h[0], h[1]);
        H[2 * i + 1] = __halves2bfloat162(h[2], h[3]);
        L[2 * i]     = __halves2bfloat162(l[0], l[1]);
        L[2 * i + 1] = __halves2bfloat162(l[2], l[3]);
    }
}

// ================= Flash attention via mma.sync (causal) =======================
#define AQROWS 128
#define ASROW  144
#define AQTILE (AQROWS * ASROW)         // 18432
#define AKTILE (64 * ASROW)             // 9216
#define ASTAGE (4 * AKTILE)             // 36864
#define ATTN_SMEM2 (2 * AQTILE + 2 * ASTAGE)   // 110592

__device__ __forceinline__ void attn_ld_q(const __nv_bfloat16* __restrict__ g,
                                          size_t growbase, int colbase,
                                          uint32_t dst, int tid) {
    #pragma unroll
    for (int l = 0; l < 4; l++) {
        int f = tid + (l << 8);
        int r = f >> 3;
        int u = f & 7;
        cp_async16(dst + r * ASROW + u * 16,
                   g + (growbase + r) * DMODEL + colbase + u * 8);
    }
}
__device__ __forceinline__ void attn_ld_kv(const __nv_bfloat16* __restrict__ g,
                                           size_t growbase, int colbase,
                                           uint32_t dst, int tid) {
    #pragma unroll
    for (int l = 0; l < 2; l++) {
        int f = tid + (l << 8);
        int r = f >> 3;
        int u = f & 7;
        cp_async16(dst + r * ASROW + u * 16,
                   g + (growbase + r) * DMODEL + colbase + u * 8);
    }
}

__global__ void __launch_bounds__(256, 2)
attn_mma_kernel() {
    extern __shared__ __align__(128) char asmem[];
    const uint32_t sb = smem_u32(asmem);
    const uint32_t QH = sb, QL = sb + AQTILE;
    const uint32_t ST0 = sb + 2 * AQTILE;

    const int tid  = threadIdx.x;
    const int w    = tid >> 5;
    const int lane = tid & 31;
    const int qb   = (gridDim.x - 1) - blockIdx.x;
    const int bh   = blockIdx.y;
    const int b    = bh >> 4;
    const int h    = bh & 15;

    const size_t qrow = (size_t)b * SEQ + qb * AQROWS;
    const int    hcol = h * DK;
    const int    kmax = 2 * qb + 1;

    attn_ld_q(g_qh, qrow, hcol, QH, tid);
    attn_ld_q(g_ql, qrow, hcol, QL, tid);
    cp_commit_group();
    {
        size_t krow = (size_t)b * SEQ;
        attn_ld_kv(g_kh, krow, hcol, ST0 + 0 * AKTILE, tid);
        attn_ld_kv(g_kl, krow, hcol, ST0 + 1 * AKTILE, tid);
        attn_ld_kv(g_vh, krow, hcol, ST0 + 2 * AKTILE, tid);
        attn_ld_kv(g_vl, krow, hcol, ST0 + 3 * AKTILE, tid);
        cp_commit_group();
    }
    cp_wait_group<0>();
    __syncthreads();

    const uint32_t a_off = (uint32_t)((w * 16 + (lane & 15)) * ASROW + (lane >> 4) * 16);
    uint32_t qh_a[4][4], ql_a[4][4];
    #pragma unroll
    for (int sk = 0; sk < 4; sk++) {
        ldsm4(qh_a[sk], QH + a_off + sk * 32);
        ldsm4(ql_a[sk], QL + a_off + sk * 32);
    }

    float o[8][4];
    #pragma unroll
    for (int f = 0; f < 8; f++)
        #pragma unroll
        for (int e = 0; e < 4; e++) o[f][e] = 0.f;
    float mA = -1e30f, mB = -1e30f, lA = 0.f, lB = 0.f;

    const uint32_t kb_off = (uint32_t)(((lane >> 4) * 8 + (lane & 7)) * ASROW
                                       + ((lane >> 3) & 1) * 16);
    const uint32_t vt_off = (uint32_t)(((lane & 7) + 8 * ((lane >> 3) & 1)) * ASROW
                                       + (lane >> 4) * 16);

    for (int kb = 0; kb <= kmax; kb++) {
        __syncthreads();
        if (kb + 1 <= kmax) {
            uint32_t st = ST0 + ((kb + 1) & 1) * ASTAGE;
            size_t krow = (size_t)b * SEQ + (size_t)(kb + 1) * 64;
            attn_ld_kv(g_kh, krow, hcol, st + 0 * AKTILE, tid);
            attn_ld_kv(g_kl, krow, hcol, st + 1 * AKTILE, tid);
            attn_ld_kv(g_vh, krow, hcol, st + 2 * AKTILE, tid);
            attn_ld_kv(g_vl, krow, hcol, st + 3 * AKTILE, tid);
        }
        cp_commit_group();
        cp_wait_group<1>();
        __syncthreads();

        const uint32_t st = ST0 + (kb & 1) * ASTAGE;
        const uint32_t KH = st, KL = st + AKTILE, VH = st + 2 * AKTILE, VL = st + 3 * AKTILE;

        float s[8][4];
        #pragma unroll
        for (int f = 0; f < 8; f++)
            #pragma unroll
            for (int e = 0; e < 4; e++) s[f][e] = 0.f;

        #pragma unroll
        for (int sk = 0; sk < 4; sk++) {
            #pragma unroll
            for (int np = 0; np < 4; np++) {
                uint32_t bh4[4], bl4[4];
                uint32_t base = np * 16 * ASROW + kb_off + sk * 32;
                ldsm4(bh4, KH + base);
                ldsm4(bl4, KL + base);
                #pragma unroll
                for (int half = 0; half < 2; half++) {
                    const int nf = np * 2 + half;
                    mma16816(s[nf], qh_a[sk], bh4 + half * 2);
                    mma16816(s[nf], qh_a[sk], bl4 + half * 2);
                    mma16816(s[nf], ql_a[sk], bh4 + half * 2);
                }
            }
        }

        if (kb >= 2 * qb) {
            const int rA = w * 16 + (lane >> 2);
            const int rB = rA + 8;
            const int cbase = kb * 64 - qb * AQROWS;
            #pragma unroll
            for (int f = 0; f < 8; f++) {
                const int c0 = cbase + f * 8 + (lane & 3) * 2;
                if (c0 > rA)     s[f][0] = -1e30f;
                if (c0 + 1 > rA) s[f][1] = -1e30f;
                if (c0 > rB)     s[f][2] = -1e30f;
                if (c0 + 1 > rB) s[f][3] = -1e30f;
            }
        }

        float mAn = mA, mBn = mB;
        #pragma unroll
        for (int f = 0; f < 8; f++) {
            mAn = fmaxf(mAn, fmaxf(s[f][0], s[f][1]));
            mBn = fmaxf(mBn, fmaxf(s[f][2], s[f][3]));
        }
        mAn = fmaxf(mAn, __shfl_xor_sync(0xffffffffu, mAn, 1));
        mAn = fmaxf(mAn, __shfl_xor_sync(0xffffffffu, mAn, 2));
        mBn = fmaxf(mBn, __shfl_xor_sync(0xffffffffu, mBn, 1));
        mBn = fmaxf(mBn, __shfl_xor_sync(0xffffffffu, mBn, 2));

        const float alA = __expf(mA - mAn);
        const float alB = __expf(mB - mBn);
        float sumA = 0.f, sumB = 0.f;
        #pragma unroll
        for (int f = 0; f < 8; f++) {
            s[f][0] = __expf(s[f][0] - mAn);
            s[f][1] = __expf(s[f][1] - mAn);
            s[f][2] = __expf(s[f][2] - mBn);
            s[f][3] = __expf(s[f][3] - mBn);
            sumA += s[f][0] + s[f][1];
            sumB += s[f][2] + s[f][3];
        }
        sumA += __shfl_xor_sync(0xffffffffu, sumA, 1);
        sumA += __shfl_xor_sync(0xffffffffu, sumA, 2);
        sumB += __shfl_xor_sync(0xffffffffu, sumB, 1);
        sumB += __shfl_xor_sync(0xffffffffu, sumB, 2);
        lA = lA * alA + sumA;
        lB = lB * alB + sumB;
        mA = mAn; mB = mBn;

        #pragma unroll
        for (int f = 0; f < 8; f++) {
            o[f][0] *= alA; o[f][1] *= alA;
            o[f][2] *= alB; o[f][3] *= alB;
        }

        #pragma unroll
        for (int t = 0; t < 4; t++) {
            const int f0 = 2 * t, f1 = 2 * t + 1;
            uint32_t ah[4], al[4];
            ah[0] = pack_bf16x2(s[f0][0], s[f0][1]);
            ah[1] = pack_bf16x2(s[f0][2], s[f0][3]);
            ah[2] = pack_bf16x2(s[f1][0], s[f1][1]);
            ah[3] = pack_bf16x2(s[f1][2], s[f1][3]);
            {
                float r00 = s[f0][0] - __bfloat162float(__float2bfloat16(s[f0][0]));
                float r01 = s[f0][1] - __bfloat162float(__float2bfloat16(s[f0][1]));
                float r02 = s[f0][2] - __bfloat162float(__float2bfloat16(s[f0][2]));
                float r03 = s[f0][3] - __bfloat162float(__float2bfloat16(s[f0][3]));
                float r10 = s[f1][0] - __bfloat162float(__float2bfloat16(s[f1][0]));
                float r11 = s[f1][1] - __bfloat162float(__float2bfloat16(s[f1][1]));
                float r12 = s[f1][2] - __bfloat162float(__float2bfloat16(s[f1][2]));
                float r13 = s[f1][3] - __bfloat162float(__float2bfloat16(s[f1][3]));
                al[0] = pack_bf16x2(r00, r01);
                al[1] = pack_bf16x2(r02, r03);
                al[2] = pack_bf16x2(r10, r11);
                al[3] = pack_bf16x2(r12, r13);
            }
            #pragma unroll
            for (int u = 0; u < 4; u++) {
                uint32_t vh4[4], vl4[4];
                uint32_t base = (t * 16) * ASROW + u * 32 + vt_off;
                ldsm4t(vh4, VH + base);
                ldsm4t(vl4, VL + base);
                mma16816(o[2 * u],     ah, vh4);
                mma16816(o[2 * u],     ah, vl4);
                mma16816(o[2 * u],     al, vh4);
                mma16816(o[2 * u + 1], ah, vh4 + 2);
                mma16816(o[2 * u + 1], ah, vl4 + 2);
                mma16816(o[2 * u + 1], al, vh4 + 2);
            }
        }
    }

    const float invA = 1.f / fmaxf(lA, 1e-9f);
    const float invB = 1.f / fmaxf(lB, 1e-9f);
    const size_t rowA = qrow + w * 16 + (lane >> 2);
    const size_t rowB = rowA + 8;
    #pragma unroll
    for (int f = 0; f < 8; f++) {
        const int col = hcol + f * 8 + (lane & 3) * 2;
        float vA0 = o[f][0] * invA, vA1 = o[f][1] * invA;
        float vB0 = o[f][2] * invB, vB1 = o[f][3] * invB;
        __nv_bfloat16 hA0 = __float2bfloat16(vA0), hA1 = __float2bfloat16(vA1);
        __nv_bfloat16 hB0 = __float2bfloat16(vB0), hB1 = __float2bfloat16(vB1);
        *(__nv_bfloat162*)(g_ch + rowA * DMODEL + col) = __halves2bfloat162(hA0, hA1);
        *(__nv_bfloat162*)(g_ch + rowB * DMODEL + col) = __halves2bfloat162(hB0, hB1);
        *(__nv_bfloat162*)(g_cl + rowA * DMODEL + col) =
            __halves2bfloat162(__float2bfloat16(vA0 - __bfloat162float(hA0)),
                               __float2bfloat16(vA1 - __bfloat162float(hA1)));
        *(__nv_bfloat162*)(g_cl + rowB * DMODEL + col) =
            __halves2bfloat162(__float2bfloat16(vB0 - __bfloat162float(hB0)),
                               __float2bfloat16(vB1 - __bfloat162float(hB1)));
    }
}

// ================= launch ======================================================
extern "C" void kernel_launch(void* const* d_in, const int* in_sizes, int n_in,
                              void* d_out, int out_size)
{
    (void)in_sizes; (void)n_in; (void)out_size;
    const float* x  = (const float*)d_in[0];
    const float* wq = (const float*)d_in[1];
    const float* wk = (const float*)d_in[2];
    const float* wv = (const float*)d_in[3];
    const float* wo = (const float*)d_in[4];
    float* out = (float*)d_out;

    static cudaError_t a1 = cudaFuncSetAttribute(
        attn_mma_kernel, cudaFuncAttributeMaxDynamicSharedMemorySize, ATTN_SMEM2);
    static cudaError_t a2 = cudaFuncSetAttribute(
        gemm_qkv_tc, cudaFuncAttributeMaxDynamicSharedMemorySize, GEMM_SMEM);
    static cudaError_t a3 = cudaFuncSetAttribute(
        gemm_out_tc, cudaFuncAttributeMaxDynamicSharedMemorySize, GEMM_SMEM);
    (void)a1; (void)a2; (void)a3;

    __nv_bfloat16 *xh, *xl, *wh, *wl;
    cudaGetSymbolAddress((void**)&xh, g_xh);
    cudaGetSymbolAddress((void**)&xl, g_xl);
    cudaGetSymbolAddress((void**)&wh, g_wh);
    cudaGetSymbolAddress((void**)&wl, g_wl);

    const int NX = MROWS * DMODEL / 4;
    const int NW = DMODEL * DMODEL / 4;
    const size_t WSZ = (size_t)DMODEL * DMODEL;

    split_kernel<<<2048, 256>>>(x, xh, xl, NX);
    split2_kernel<<<dim3(512, 1, 2), 256>>>(wq, wk,
        wh + 0 * WSZ, wl + 0 * WSZ, wh + 1 * WSZ, wl + 1 * WSZ, NW);
    split2_kernel<<<dim3(512, 1, 2), 256>>>(wv, wo,
        wh + 2 * WSZ, wl + 2 * WSZ, wh + 3 * WSZ, wl + 3 * WSZ, NW);

    dim3 gqkv(DMODEL / BN, MROWS / BM, 3);
    gemm_qkv_tc<<<gqkv, 256, GEMM_SMEM>>>();

    dim3 gattn(SEQ / AQROWS, BATCH * NHEAD);
    attn_mma_kernel<<<gattn, 256, ATTN_SMEM2>>>();

    dim3 gout(DMODEL / BN, MROWS / BM);
    gemm_out_tc<<<gout, 256, GEMM_SMEM>>>(out);
}

// round 7
// speedup vs baseline: 3.1835x; 1.0669x over previous
#include <cuda_runtime.h>
#include <cuda_bf16.h>
#include <cuda_fp16.h>
#include <cstdint>
#include <math.h>

#define BATCH  4
#define SEQ    2048
#define DMODEL 1024
#define NHEAD  16
#define DK     64
#define MROWS  (BATCH*SEQ)   // 8192

// ---------------- scratch (device globals: allocation-free rule) ----------------
__device__ __nv_bfloat16 g_xh[(size_t)MROWS * DMODEL];
__device__ __nv_bfloat16 g_xl[(size_t)MROWS * DMODEL];
__device__ __nv_bfloat16 g_qh[(size_t)MROWS * DMODEL];
__device__ __nv_bfloat16 g_ql[(size_t)MROWS * DMODEL];
__device__ __nv_bfloat16 g_kh[(size_t)MROWS * DMODEL];
__device__ __nv_bfloat16 g_kl[(size_t)MROWS * DMODEL];
__device__ __half        g_vf[(size_t)MROWS * DMODEL];   // V single fp16
__device__ __nv_bfloat16 g_ch[(size_t)MROWS * DMODEL];
__device__ __nv_bfloat16 g_cl[(size_t)MROWS * DMODEL];
__device__ __nv_bfloat16 g_wh[4][(size_t)DMODEL * DMODEL];
__device__ __nv_bfloat16 g_wl[4][(size_t)DMODEL * DMODEL];

// ================= PTX helpers (portable sm_80-class only) =====================
__device__ __forceinline__ uint32_t smem_u32(const void* p) {
    uint32_t a;
    asm("{ .reg .u64 t; cvta.to.shared.u64 t, %1; cvt.u32.u64 %0, t; }" : "=r"(a) : "l"(p));
    return a;
}
template <int N> __device__ __forceinline__ void cp_wait_group() {
    asm volatile("cp.async.wait_group %0;" :: "n"(N) : "memory");
}
__device__ __forceinline__ void cp_commit_group() {
    asm volatile("cp.async.commit_group;" ::: "memory");
}
__device__ __forceinline__ void cp_async16(uint32_t dst, const void* src) {
    asm volatile("cp.async.cg.shared.global [%0], [%1], 16;" :: "r"(dst), "l"(src) : "memory");
}
__device__ __forceinline__ void ldsm4(uint32_t* r, uint32_t addr) {
    asm volatile("ldmatrix.sync.aligned.m8n8.x4.shared.b16 {%0,%1,%2,%3}, [%4];"
                 : "=r"(r[0]), "=r"(r[1]), "=r"(r[2]), "=r"(r[3]) : "r"(addr));
}
__device__ __forceinline__ void ldsm4t(uint32_t* r, uint32_t addr) {
    asm volatile("ldmatrix.sync.aligned.m8n8.x4.trans.shared.b16 {%0,%1,%2,%3}, [%4];"
                 : "=r"(r[0]), "=r"(r[1]), "=r"(r[2]), "=r"(r[3]) : "r"(addr));
}
__device__ __forceinline__ void mma16816(float* c, const uint32_t* a, const uint32_t* b) {
    asm volatile(
        "mma.sync.aligned.m16n8k16.row.col.f32.bf16.bf16.f32 "
        "{%0,%1,%2,%3}, {%4,%5,%6,%7}, {%8,%9}, {%0,%1,%2,%3};"
        : "+f"(c[0]), "+f"(c[1]), "+f"(c[2]), "+f"(c[3])
        : "r"(a[0]), "r"(a[1]), "r"(a[2]), "r"(a[3]), "r"(b[0]), "r"(b[1]));
}
__device__ __forceinline__ void mma16816h(float* c, const uint32_t* a, const uint32_t* b) {
    asm volatile(
        "mma.sync.aligned.m16n8k16.row.col.f32.f16.f16.f32 "
        "{%0,%1,%2,%3}, {%4,%5,%6,%7}, {%8,%9}, {%0,%1,%2,%3};"
        : "+f"(c[0]), "+f"(c[1]), "+f"(c[2]), "+f"(c[3])
        : "r"(a[0]), "r"(a[1]), "r"(a[2]), "r"(a[3]), "r"(b[0]), "r"(b[1]));
}
__device__ __forceinline__ uint32_t pack_h16x2(float lo, float hi) {
    __half2 t = __floats2half2_rn(lo, hi);
    return *(uint32_t*)&t;
}

// ================= bf16-split GEMM-NT via mma.sync =============================
// BK=16, 4-stage cp.async pipeline; 2 CTA/SM.
#define BM 128
#define BN 128
#define BK 16
#define NST 4
#define NCHUNK (DMODEL / BK)        // 64
#define SROW 48                      // 32B data + 16B pad
#define TILE_SM (128 * SROW)         // 6144
#define STAGE_SM (4 * TILE_SM)       // 24576 (Ah, Al, Wh, Wl)
#define GEMM_SMEM (NST * STAGE_SM)   // 98304 -> 2 CTA/SM

__device__ __forceinline__ void ld_tile(const __nv_bfloat16* __restrict__ g,
                                        int rowbase, int k0, uint32_t dst, int tid) {
    int r = tid >> 1;                 // row 0..127
    int u = tid & 1;                  // 16B unit
    const __nv_bfloat16* src = g + (size_t)(rowbase + r) * DMODEL + k0 + u * 8;
    cp_async16(dst + r * SROW + u * 16, src);
}

__device__ __forceinline__ void gemm_core(const __nv_bfloat16* __restrict__ Ah,
                                          const __nv_bfloat16* __restrict__ Al,
                                          const __nv_bfloat16* __restrict__ Wh,
                                          const __nv_bfloat16* __restrict__ Wl,
                                          int rowA, int rowB,
                                          float acc[4][4][4]) {
    extern __shared__ __align__(128) char smem[];
    const uint32_t sb = smem_u32(smem);
    const int tid  = threadIdx.x;
    const int wid  = tid >> 5;
    const int lane = tid & 31;
    const int wm   = wid >> 2;
    const int wn   = wid & 3;

    #pragma unroll
    for (int i = 0; i < 4; i++)
        #pragma unroll
        for (int j = 0; j < 4; j++)
            #pragma unroll
            for (int e = 0; e < 4; e++) acc[i][j][e] = 0.f;

    const uint32_t a_off = (uint32_t)((wm * 64 + (lane & 15)) * SROW + (lane >> 4) * 16);
    const uint32_t b_off = (uint32_t)((wn * 32 + (lane >> 4) * 8 + (lane & 7)) * SROW
                                      + ((lane >> 3) & 1) * 16);

    #pragma unroll
    for (int s = 0; s < NST; s++) {
        uint32_t st = sb + s * STAGE_SM;
        ld_tile(Ah, rowA, s * BK, st + 0 * TILE_SM, tid);
        ld_tile(Al, rowA, s * BK, st + 1 * TILE_SM, tid);
        ld_tile(Wh, rowB, s * BK, st + 2 * TILE_SM, tid);
        ld_tile(Wl, rowB, s * BK, st + 3 * TILE_SM, tid);
        cp_commit_group();
    }

    for (int c = 0; c < NCHUNK; c++) {
        cp_wait_group<NST - 1>();
        __syncthreads();

        const uint32_t st = sb + (c % NST) * STAGE_SM;
        uint32_t bh[8], bl[8];
        ldsm4(bh,     st + 2 * TILE_SM + b_off);
        ldsm4(bh + 4, st + 2 * TILE_SM + b_off + 16 * SROW);
        ldsm4(bl,     st + 3 * TILE_SM + b_off);
        ldsm4(bl + 4, st + 3 * TILE_SM + b_off + 16 * SROW);
        #pragma unroll
        for (int mf = 0; mf < 4; mf++) {
            uint32_t ah[4], al[4];
            ldsm4(ah, st + 0 * TILE_SM + a_off + mf * 16 * SROW);
            ldsm4(al, st + 1 * TILE_SM + a_off + mf * 16 * SROW);
            #pragma unroll
            for (int nf = 0; nf < 4; nf++) {
                mma16816(acc[mf][nf], ah, bh + nf * 2);
                mma16816(acc[mf][nf], ah, bl + nf * 2);
                mma16816(acc[mf][nf], al, bh + nf * 2);
            }
        }
        __syncthreads();

        if (c + NST < NCHUNK) {
            int k0 = (c + NST) * BK;
            ld_tile(Ah, rowA, k0, st + 0 * TILE_SM, tid);
            ld_tile(Al, rowA, k0, st + 1 * TILE_SM, tid);
            ld_tile(Wh, rowB, k0, st + 2 * TILE_SM, tid);
            ld_tile(Wl, rowB, k0, st + 3 * TILE_SM, tid);
        }
        cp_commit_group();
    }
}

__global__ void __launch_bounds__(256, 2)
gemm_qkv_tc() {
    const int w = blockIdx.z;
    const float scale = (w == 0) ? 0.125f : 1.0f;

    const int rowA = blockIdx.y * BM;
    const int rowB = blockIdx.x * BN;
    float acc[4][4][4];
    gemm_core(g_xh, g_xl, g_wh[w], g_wl[w], rowA, rowB, acc);

    const int lane = threadIdx.x & 31;
    const int wid  = threadIdx.x >> 5;
    const int wm   = wid >> 2, wn = wid & 3;
    const int r0c  = lane >> 2;
    const int cc   = (lane & 3) * 2;

    if (w == 2) {
        // V: single fp16
        #pragma unroll
        for (int mf = 0; mf < 4; mf++) {
            const int mrow = rowA + wm * 64 + mf * 16;
            #pragma unroll
            for (int nf = 0; nf < 4; nf++) {
                const int col = rowB + wn * 32 + nf * 8 + cc;
                #pragma unroll
                for (int half = 0; half < 2; half++) {
                    size_t idx = (size_t)(mrow + r0c + half * 8) * DMODEL + col;
                    *(__half2*)(g_vf + idx) =
                        __floats2half2_rn(acc[mf][nf][half * 2 + 0],
                                          acc[mf][nf][half * 2 + 1]);
                }
            }
        }
    } else {
        __nv_bfloat16* H = (w == 0) ? g_qh : g_kh;
        __nv_bfloat16* L = (w == 0) ? g_ql : g_kl;
        #pragma unroll
        for (int mf = 0; mf < 4; mf++) {
            const int mrow = rowA + wm * 64 + mf * 16;
            #pragma unroll
            for (int nf = 0; nf < 4; nf++) {
                const int col = rowB + wn * 32 + nf * 8 + cc;
                #pragma unroll
                for (int half = 0; half < 2; half++) {
                    float v0 = acc[mf][nf][half * 2 + 0] * scale;
                    float v1 = acc[mf][nf][half * 2 + 1] * scale;
                    __nv_bfloat16 h0 = __float2bfloat16(v0);
                    __nv_bfloat16 h1 = __float2bfloat16(v1);
                    float l0 = v0 - __bfloat162float(h0);
                    float l1 = v1 - __bfloat162float(h1);
                    size_t idx = (size_t)(mrow + r0c + half * 8) * DMODEL + col;
                    *(__nv_bfloat162*)(H + idx) = __halves2bfloat162(h0, h1);
                    *(__nv_bfloat162*)(L + idx) = __halves2bfloat162(__float2bfloat16(l0),
                                                                     __float2bfloat16(l1));
                }
            }
        }
    }
}

__global__ void __launch_bounds__(256, 2)
gemm_out_tc(float* __restrict__ out) {
    const int rowA = blockIdx.y * BM;
    const int rowB = blockIdx.x * BN;
    float acc[4][4][4];
    gemm_core(g_ch, g_cl, g_wh[3], g_wl[3], rowA, rowB, acc);

    const int lane = threadIdx.x & 31;
    const int wid  = threadIdx.x >> 5;
    const int wm   = wid >> 2, wn = wid & 3;
    const int r0c  = lane >> 2;
    const int cc   = (lane & 3) * 2;
    #pragma unroll
    for (int mf = 0; mf < 4; mf++) {
        const int mrow = rowA + wm * 64 + mf * 16;
        #pragma unroll
        for (int nf = 0; nf < 4; nf++) {
            const int col = rowB + wn * 32 + nf * 8 + cc;
            *(float2*)(out + (size_t)(mrow + r0c) * DMODEL + col) =
                make_float2(acc[mf][nf][0], acc[mf][nf][1]);
            *(float2*)(out + (size_t)(mrow + r0c + 8) * DMODEL + col) =
                make_float2(acc[mf][nf][2], acc[mf][nf][3]);
        }
    }
}

// ================= fp32 -> bf16 hi/lo splits ===================================
__global__ void __launch_bounds__(256)
split_kernel(const float* __restrict__ in, __nv_bfloat16* __restrict__ hi,
             __nv_bfloat16* __restrict__ lo, int n4) {
    __nv_bfloat162* H = (__nv_bfloat162*)hi;
    __nv_bfloat162* L = (__nv_bfloat162*)lo;
    for (int i = blockIdx.x * blockDim.x + threadIdx.x; i < n4;
         i += gridDim.x * blockDim.x) {
        float4 v = ((const float4*)in)[i];
        float a[4] = {v.x, v.y, v.z, v.w};
        __nv_bfloat16 h[4], l[4];
        #pragma unroll
        for (int j = 0; j < 4; j++) {
            h[j] = __float2bfloat16(a[j]);
            l[j] = __float2bfloat16(a[j] - __bfloat162float(h[j]));
        }
        H[2 * i]     = __halves2bfloat162(h[0], h[1]);
        H[2 * i + 1] = __halves2bfloat162(h[2], h[3]);
        L[2 * i]     = __halves2bfloat162(l[0], l[1]);
        L[2 * i + 1] = __halves2bfloat162(l[2], l[3]);
    }
}

__global__ void __launch_bounds__(256)
split2_kernel(const float* __restrict__ in0, const float* __restrict__ in1,
              __nv_bfloat16* __restrict__ hi0, __nv_bfloat16* __restrict__ lo0,
              __nv_bfloat16* __restrict__ hi1, __nv_bfloat16* __restrict__ lo1,
              int n4) {
    const float* in = blockIdx.z ? in1 : in0;
    __nv_bfloat162* H = (__nv_bfloat162*)(blockIdx.z ? hi1 : hi0);
    __nv_bfloat162* L = (__nv_bfloat162*)(blockIdx.z ? lo1 : lo0);
    for (int i = blockIdx.x * blockDim.x + threadIdx.x; i < n4;
         i += gridDim.x * blockDim.x) {
        float4 v = ((const float4*)in)[i];
        float a[4] = {v.x, v.y, v.z, v.w};
        __nv_bfloat16 h[4], l[4];
        #pragma unroll
        for (int j = 0; j < 4; j++) {
            h[j] = __float2bfloat16(a[j]);
            l[j] = __float2bfloat16(a[j] - __bfloat162float(h[j]));
        }
        H[2 * i]     = __halves2bfloat162(h[0], h[1]);
        H[2 * i + 1] = __halves2bfloat162(h[2], h[3]);
        L[2 * i]     = __halves2bfloat162(l[0], l[1]);
        L[2 * i + 1] = __halves2bfloat162(l[2], l[3]);
    }
}

// ================= Flash attention via mma.sync (causal) =======================
// S = QhKh+QhKl+QlKh (bf16 3-pass); PV = P_f16 x V_f16 single pass.
#define AQROWS 128
#define ASROW  144
#define AQTILE (AQROWS * ASROW)         // 18432
#define AKTILE (64 * ASROW)             // 9216
#define ASTAGE (3 * AKTILE)             // kh, kl, vf = 27648
#define ATTN_SMEM2 (2 * AQTILE + 2 * ASTAGE)   // 92160

__device__ __forceinline__ void attn_ld_q(const __nv_bfloat16* __restrict__ g,
                                          size_t growbase, int colbase,
                                          uint32_t dst, int tid) {
    #pragma unroll
    for (int l = 0; l < 4; l++) {
        int f = tid + (l << 8);
        int r = f >> 3;
        int u = f & 7;
        cp_async16(dst + r * ASROW + u * 16,
                   g + (growbase + r) * DMODEL + colbase + u * 8);
    }
}
__device__ __forceinline__ void attn_ld_kv(const __nv_bfloat16* __restrict__ g,
                                           size_t growbase, int colbase,
                                           uint32_t dst, int tid) {
    #pragma unroll
    for (int l = 0; l < 2; l++) {
        int f = tid + (l << 8);
        int r = f >> 3;
        int u = f & 7;
        cp_async16(dst + r * ASROW + u * 16,
                   g + (growbase + r) * DMODEL + colbase + u * 8);
    }
}

__global__ void __launch_bounds__(256, 2)
attn_mma_kernel() {
    extern __shared__ __align__(128) char asmem[];
    const uint32_t sb = smem_u32(asmem);
    const uint32_t QH = sb, QL = sb + AQTILE;
    const uint32_t ST0 = sb + 2 * AQTILE;

    const int tid  = threadIdx.x;
    const int w    = tid >> 5;
    const int lane = tid & 31;
    const int qb   = (gridDim.x - 1) - blockIdx.x;
    const int bh   = blockIdx.y;
    const int b    = bh >> 4;
    const int h    = bh & 15;

    const size_t qrow = (size_t)b * SEQ + qb * AQROWS;
    const int    hcol = h * DK;
    const int    kmax = 2 * qb + 1;

    attn_ld_q(g_qh, qrow, hcol, QH, tid);
    attn_ld_q(g_ql, qrow, hcol, QL, tid);
    cp_commit_group();
    {
        size_t krow = (size_t)b * SEQ;
        attn_ld_kv(g_kh, krow, hcol, ST0 + 0 * AKTILE, tid);
        attn_ld_kv(g_kl, krow, hcol, ST0 + 1 * AKTILE, tid);
        attn_ld_kv((const __nv_bfloat16*)g_vf, krow, hcol, ST0 + 2 * AKTILE, tid);
        cp_commit_group();
    }
    cp_wait_group<0>();
    __syncthreads();

    const uint32_t a_off = (uint32_t)((w * 16 + (lane & 15)) * ASROW + (lane >> 4) * 16);
    uint32_t qh_a[4][4], ql_a[4][4];
    #pragma unroll
    for (int sk = 0; sk < 4; sk++) {
        ldsm4(qh_a[sk], QH + a_off + sk * 32);
        ldsm4(ql_a[sk], QL + a_off + sk * 32);
    }

    float o[8][4];
    #pragma unroll
    for (int f = 0; f < 8; f++)
        #pragma unroll
        for (int e = 0; e < 4; e++) o[f][e] = 0.f;
    float mA = -1e30f, mB = -1e30f, lA = 0.f, lB = 0.f;

    const uint32_t kb_off = (uint32_t)(((lane >> 4) * 8 + (lane & 7)) * ASROW
                                       + ((lane >> 3) & 1) * 16);
    const uint32_t vt_off = (uint32_t)(((lane & 7) + 8 * ((lane >> 3) & 1)) * ASROW
                                       + (lane >> 4) * 16);

    for (int kb = 0; kb <= kmax; kb++) {
        __syncthreads();
        if (kb + 1 <= kmax) {
            uint32_t st = ST0 + ((kb + 1) & 1) * ASTAGE;
            size_t krow = (size_t)b * SEQ + (size_t)(kb + 1) * 64;
            attn_ld_kv(g_kh, krow, hcol, st + 0 * AKTILE, tid);
            attn_ld_kv(g_kl, krow, hcol, st + 1 * AKTILE, tid);
            attn_ld_kv((const __nv_bfloat16*)g_vf, krow, hcol, st + 2 * AKTILE, tid);
        }
        cp_commit_group();
        cp_wait_group<1>();
        __syncthreads();

        const uint32_t st = ST0 + (kb & 1) * ASTAGE;
        const uint32_t KH = st, KL = st + AKTILE, VF = st + 2 * AKTILE;

        float s[8][4];
        #pragma unroll
        for (int f = 0; f < 8; f++)
            #pragma unroll
            for (int e = 0; e < 4; e++) s[f][e] = 0.f;

        #pragma unroll
        for (int sk = 0; sk < 4; sk++) {
            #pragma unroll
            for (int np = 0; np < 4; np++) {
                uint32_t bh4[4], bl4[4];
                uint32_t base = np * 16 * ASROW + kb_off + sk * 32;
                ldsm4(bh4, KH + base);
                ldsm4(bl4, KL + base);
                #pragma unroll
                for (int half = 0; half < 2; half++) {
                    const int nf = np * 2 + half;
                    mma16816(s[nf], qh_a[sk], bh4 + half * 2);
                    mma16816(s[nf], qh_a[sk], bl4 + half * 2);
                    mma16816(s[nf], ql_a[sk], bh4 + half * 2);
                }
            }
        }

        if (kb >= 2 * qb) {
            const int rA = w * 16 + (lane >> 2);
            const int rB = rA + 8;
            const int cbase = kb * 64 - qb * AQROWS;
            #pragma unroll
            for (int f = 0; f < 8; f++) {
                const int c0 = cbase + f * 8 + (lane & 3) * 2;
                if (c0 > rA)     s[f][0] = -1e30f;
                if (c0 + 1 > rA) s[f][1] = -1e30f;
                if (c0 > rB)     s[f][2] = -1e30f;
                if (c0 + 1 > rB) s[f][3] = -1e30f;
            }
        }

        float mAn = mA, mBn = mB;
        #pragma unroll
        for (int f = 0; f < 8; f++) {
            mAn = fmaxf(mAn, fmaxf(s[f][0], s[f][1]));
            mBn = fmaxf(mBn, fmaxf(s[f][2], s[f][3]));
        }
        mAn = fmaxf(mAn, __shfl_xor_sync(0xffffffffu, mAn, 1));
        mAn = fmaxf(mAn, __shfl_xor_sync(0xffffffffu, mAn, 2));
        mBn = fmaxf(mBn, __shfl_xor_sync(0xffffffffu, mBn, 1));
        mBn = fmaxf(mBn, __shfl_xor_sync(0xffffffffu, mBn, 2));

        const float alA = __expf(mA - mAn);
        const float alB = __expf(mB - mBn);
        float sumA = 0.f, sumB = 0.f;
        #pragma unroll
        for (int f = 0; f < 8; f++) {
            s[f][0] = __expf(s[f][0] - mAn);
            s[f][1] = __expf(s[f][1] - mAn);
            s[f][2] = __expf(s[f][2] - mBn);
            s[f][3] = __expf(s[f][3] - mBn);
            sumA += s[f][0] + s[f][1];
            sumB += s[f][2] + s[f][3];
        }
        sumA += __shfl_xor_sync(0xffffffffu, sumA, 1);
        sumA += __shfl_xor_sync(0xffffffffu, sumA, 2);
        sumB += __shfl_xor_sync(0xffffffffu, sumB, 1);
        sumB += __shfl_xor_sync(0xffffffffu, sumB, 2);
        lA = lA * alA + sumA;
        lB = lB * alB + sumB;
        mA = mAn; mB = mBn;

        #pragma unroll
        for (int f = 0; f < 8; f++) {
            o[f][0] *= alA; o[f][1] *= alA;
            o[f][2] *= alB; o[f][3] *= alB;
        }

        // ---- O += P V : fp16 single pass ----
        #pragma unroll
        for (int t = 0; t < 4; t++) {
            const int f0 = 2 * t, f1 = 2 * t + 1;
            uint32_t ap[4];
            ap[0] = pack_h16x2(s[f0][0], s[f0][1]);
            ap[1] = pack_h16x2(s[f0][2], s[f0][3]);
            ap[2] = pack_h16x2(s[f1][0], s[f1][1]);
            ap[3] = pack_h16x2(s[f1][2], s[f1][3]);
            #pragma unroll
            for (int u = 0; u < 4; u++) {
                uint32_t vf4[4];
                uint32_t base = (t * 16) * ASROW + u * 32 + vt_off;
                ldsm4t(vf4, VF + base);
                mma16816h(o[2 * u],     ap, vf4);
                mma16816h(o[2 * u + 1], ap, vf4 + 2);
            }
        }
    }

    const float invA = 1.f / fmaxf(lA, 1e-9f);
    const float invB = 1.f / fmaxf(lB, 1e-9f);
    const size_t rowA = qrow + w * 16 + (lane >> 2);
    const size_t rowB = rowA + 8;
    #pragma unroll
    for (int f = 0; f < 8; f++) {
        const int col = hcol + f * 8 + (lane & 3) * 2;
        float vA0 = o[f][0] * invA, vA1 = o[f][1] * invA;
        float vB0 = o[f][2] * invB, vB1 = o[f][3] * invB;
        __nv_bfloat16 hA0 = __float2bfloat16(vA0), hA1 = __float2bfloat16(vA1);
        __nv_bfloat16 hB0 = __float2bfloat16(vB0), hB1 = __float2bfloat16(vB1);
        *(__nv_bfloat162*)(g_ch + rowA * DMODEL + col) = __halves2bfloat162(hA0, hA1);
        *(__nv_bfloat162*)(g_ch + rowB * DMODEL + col) = __halves2bfloat162(hB0, hB1);
        *(__nv_bfloat162*)(g_cl + rowA * DMODEL + col) =
            __halves2bfloat162(__float2bfloat16(vA0 - __bfloat162float(hA0)),
                               __float2bfloat16(vA1 - __bfloat162float(hA1)));
        *(__nv_bfloat162*)(g_cl + rowB * DMODEL + col) =
            __halves2bfloat162(__float2bfloat16(vB0 - __bfloat162float(hB0)),
                               __float2bfloat16(vB1 - __bfloat162float(hB1)));
    }
}

// ================= launch ======================================================
extern "C" void kernel_launch(void* const* d_in, const int* in_sizes, int n_in,
                              void* d_out, int out_size)
{
    (void)in_sizes; (void)n_in; (void)out_size;
    const float* x  = (const float*)d_in[0];
    const float* wq = (const float*)d_in[1];
    const float* wk = (const float*)d_in[2];
    const float* wv = (const float*)d_in[3];
    const float* wo = (const float*)d_in[4];
    float* out = (float*)d_out;

    static cudaError_t a1 = cudaFuncSetAttribute(
        attn_mma_kernel, cudaFuncAttributeMaxDynamicSharedMemorySize, ATTN_SMEM2);
    static cudaError_t a2 = cudaFuncSetAttribute(
        gemm_qkv_tc, cudaFuncAttributeMaxDynamicSharedMemorySize, GEMM_SMEM);
    static cudaError_t a3 = cudaFuncSetAttribute(
        gemm_out_tc, cudaFuncAttributeMaxDynamicSharedMemorySize, GEMM_SMEM);
    (void)a1; (void)a2; (void)a3;

    __nv_bfloat16 *xh, *xl, *wh, *wl;
    cudaGetSymbolAddress((void**)&xh, g_xh);
    cudaGetSymbolAddress((void**)&xl, g_xl);
    cudaGetSymbolAddress((void**)&wh, g_wh);
    cudaGetSymbolAddress((void**)&wl, g_wl);

    const int NX = MROWS * DMODEL / 4;
    const int NW = DMODEL * DMODEL / 4;
    const size_t WSZ = (size_t)DMODEL * DMODEL;

    split_kernel<<<2048, 256>>>(x, xh, xl, NX);
    split2_kernel<<<dim3(512, 1, 2), 256>>>(wq, wk,
        wh + 0 * WSZ, wl + 0 * WSZ, wh + 1 * WSZ, wl + 1 * WSZ, NW);
    split2_kernel<<<dim3(512, 1, 2), 256>>>(wv, wo,
        wh + 2 * WSZ, wl + 2 * WSZ, wh + 3 * WSZ, wl + 3 * WSZ, NW);

    dim3 gqkv(DMODEL / BN, MROWS / BM, 3);
    gemm_qkv_tc<<<gqkv, 256, GEMM_SMEM>>>();

    dim3 gattn(SEQ / AQROWS, BATCH * NHEAD);
    attn_mma_kernel<<<gattn, 256, ATTN_SMEM2>>>();

    dim3 gout(DMODEL / BN, MROWS / BM);
    gemm_out_tc<<<gout, 256, GEMM_SMEM>>>(out);
}

// round 9
// speedup vs baseline: 3.2627x; 1.0249x over previous
#include <cuda_runtime.h>
#include <cuda_bf16.h>
#include <cuda_fp16.h>
#include <cstdint>
#include <math.h>

#define BATCH  4
#define SEQ    2048
#define DMODEL 1024
#define NHEAD  16
#define DK     64
#define MROWS  (BATCH*SEQ)   // 8192

// ---------------- scratch (device globals: allocation-free rule) ----------------
__device__ __nv_bfloat16 g_xh[(size_t)MROWS * DMODEL];
__device__ __nv_bfloat16 g_xl[(size_t)MROWS * DMODEL];
__device__ __nv_bfloat16 g_qh[(size_t)MROWS * DMODEL];
__device__ __nv_bfloat16 g_ql[(size_t)MROWS * DMODEL];
__device__ __nv_bfloat16 g_kh[(size_t)MROWS * DMODEL];
__device__ __nv_bfloat16 g_kl[(size_t)MROWS * DMODEL];
__device__ __half        g_vf[(size_t)MROWS * DMODEL];   // V single fp16
__device__ __nv_bfloat16 g_ch[(size_t)MROWS * DMODEL];
__device__ __nv_bfloat16 g_cl[(size_t)MROWS * DMODEL];
__device__ __nv_bfloat16 g_wh[4][(size_t)DMODEL * DMODEL];
__device__ __nv_bfloat16 g_wl[4][(size_t)DMODEL * DMODEL];

// ================= PTX helpers (portable sm_80-class only) =====================
__device__ __forceinline__ uint32_t smem_u32(const void* p) {
    uint32_t a;
    asm("{ .reg .u64 t; cvta.to.shared.u64 t, %1; cvt.u32.u64 %0, t; }" : "=r"(a) : "l"(p));
    return a;
}
template <int N> __device__ __forceinline__ void cp_wait_group() {
    asm volatile("cp.async.wait_group %0;" :: "n"(N) : "memory");
}
__device__ __forceinline__ void cp_commit_group() {
    asm volatile("cp.async.commit_group;" ::: "memory");
}
__device__ __forceinline__ void cp_async16(uint32_t dst, const void* src) {
    asm volatile("cp.async.cg.shared.global [%0], [%1], 16;" :: "r"(dst), "l"(src) : "memory");
}
__device__ __forceinline__ void ldsm4(uint32_t* r, uint32_t addr) {
    asm volatile("ldmatrix.sync.aligned.m8n8.x4.shared.b16 {%0,%1,%2,%3}, [%4];"
                 : "=r"(r[0]), "=r"(r[1]), "=r"(r[2]), "=r"(r[3]) : "r"(addr));
}
__device__ __forceinline__ void ldsm4t(uint32_t* r, uint32_t addr) {
    asm volatile("ldmatrix.sync.aligned.m8n8.x4.trans.shared.b16 {%0,%1,%2,%3}, [%4];"
                 : "=r"(r[0]), "=r"(r[1]), "=r"(r[2]), "=r"(r[3]) : "r"(addr));
}
__device__ __forceinline__ void mma16816(float* c, const uint32_t* a, const uint32_t* b) {
    asm volatile(
        "mma.sync.aligned.m16n8k16.row.col.f32.bf16.bf16.f32 "
        "{%0,%1,%2,%3}, {%4,%5,%6,%7}, {%8,%9}, {%0,%1,%2,%3};"
        : "+f"(c[0]), "+f"(c[1]), "+f"(c[2]), "+f"(c[3])
        : "r"(a[0]), "r"(a[1]), "r"(a[2]), "r"(a[3]), "r"(b[0]), "r"(b[1]));
}
__device__ __forceinline__ void mma16816h(float* c, const uint32_t* a, const uint32_t* b) {
    asm volatile(
        "mma.sync.aligned.m16n8k16.row.col.f32.f16.f16.f32 "
        "{%0,%1,%2,%3}, {%4,%5,%6,%7}, {%8,%9}, {%0,%1,%2,%3};"
        : "+f"(c[0]), "+f"(c[1]), "+f"(c[2]), "+f"(c[3])
        : "r"(a[0]), "r"(a[1]), "r"(a[2]), "r"(a[3]), "r"(b[0]), "r"(b[1]));
}
__device__ __forceinline__ uint32_t pack_h16x2(float lo, float hi) {
    __half2 t = __floats2half2_rn(lo, hi);
    return *(uint32_t*)&t;
}

// ================= bf16-split GEMM-NT via mma.sync =============================
// BK=16, 4 smem stages, NST-1 in flight, ONE barrier per chunk (free-stage).
#define BM 128
#define BN 128
#define BK 16
#define NST 4
#define NCHUNK (DMODEL / BK)        // 64
#define SROW 48                      // 32B data + 16B pad
#define TILE_SM (128 * SROW)         // 6144
#define STAGE_SM (4 * TILE_SM)       // 24576 (Ah, Al, Wh, Wl)
#define GEMM_SMEM (NST * STAGE_SM)   // 98304 -> 2 CTA/SM

__device__ __forceinline__ void ld_tile(const __nv_bfloat16* __restrict__ g,
                                        int rowbase, int k0, uint32_t dst, int tid) {
    int r = tid >> 1;                 // row 0..127
    int u = tid & 1;                  // 16B unit
    const __nv_bfloat16* src = g + (size_t)(rowbase + r) * DMODEL + k0 + u * 8;
    cp_async16(dst + r * SROW + u * 16, src);
}

__device__ __forceinline__ void ld_stage(const __nv_bfloat16* __restrict__ Ah,
                                         const __nv_bfloat16* __restrict__ Al,
                                         const __nv_bfloat16* __restrict__ Wh,
                                         const __nv_bfloat16* __restrict__ Wl,
                                         int rowA, int rowB, int k0,
                                         uint32_t st, int tid) {
    ld_tile(Ah, rowA, k0, st + 0 * TILE_SM, tid);
    ld_tile(Al, rowA, k0, st + 1 * TILE_SM, tid);
    ld_tile(Wh, rowB, k0, st + 2 * TILE_SM, tid);
    ld_tile(Wl, rowB, k0, st + 3 * TILE_SM, tid);
}

__device__ __forceinline__ void gemm_core(const __nv_bfloat16* __restrict__ Ah,
                                          const __nv_bfloat16* __restrict__ Al,
                                          const __nv_bfloat16* __restrict__ Wh,
                                          const __nv_bfloat16* __restrict__ Wl,
                                          int rowA, int rowB,
                                          float acc[4][4][4]) {
    extern __shared__ __align__(128) char smem[];
    const uint32_t sb = smem_u32(smem);
    const int tid  = threadIdx.x;
    const int wid  = tid >> 5;
    const int lane = tid & 31;
    const int wm   = wid >> 2;
    const int wn   = wid & 3;

    #pragma unroll
    for (int i = 0; i < 4; i++)
        #pragma unroll
        for (int j = 0; j < 4; j++)
            #pragma unroll
            for (int e = 0; e < 4; e++) acc[i][j][e] = 0.f;

    const uint32_t a_off = (uint32_t)((wm * 64 + (lane & 15)) * SROW + (lane >> 4) * 16);
    const uint32_t b_off = (uint32_t)((wn * 32 + (lane >> 4) * 8 + (lane & 7)) * SROW
                                      + ((lane >> 3) & 1) * 16);

    // prologue: fill NST-1 stages (one stage stays free)
    #pragma unroll
    for (int s = 0; s < NST - 1; s++) {
        ld_stage(Ah, Al, Wh, Wl, rowA, rowB, s * BK, sb + s * STAGE_SM, tid);
        cp_commit_group();
    }

    for (int c = 0; c < NCHUNK; c++) {
        cp_wait_group<NST - 2>();     // stage c's group complete
        __syncthreads();              // all warps done with stage (c-1)%NST

        // refill the stage freed last iteration ((c+NST-1)%NST == (c-1)%NST)
        if (c + NST - 1 < NCHUNK) {
            int s = (c + NST - 1) % NST;
            ld_stage(Ah, Al, Wh, Wl, rowA, rowB, (c + NST - 1) * BK,
                     sb + s * STAGE_SM, tid);
        }
        cp_commit_group();

        const uint32_t st = sb + (c % NST) * STAGE_SM;
        uint32_t bh[8], bl[8];
        ldsm4(bh,     st + 2 * TILE_SM + b_off);
        ldsm4(bh + 4, st + 2 * TILE_SM + b_off + 16 * SROW);
        ldsm4(bl,     st + 3 * TILE_SM + b_off);
        ldsm4(bl + 4, st + 3 * TILE_SM + b_off + 16 * SROW);
        #pragma unroll
        for (int mf = 0; mf < 4; mf++) {
            uint32_t ah[4], al[4];
            ldsm4(ah, st + 0 * TILE_SM + a_off + mf * 16 * SROW);
            ldsm4(al, st + 1 * TILE_SM + a_off + mf * 16 * SROW);
            #pragma unroll
            for (int nf = 0; nf < 4; nf++) {
                mma16816(acc[mf][nf], ah, bh + nf * 2);
                mma16816(acc[mf][nf], ah, bl + nf * 2);
                mma16816(acc[mf][nf], al, bh + nf * 2);
            }
        }
    }
}

__global__ void __launch_bounds__(256, 2)
gemm_qkv_tc() {
    const int w = blockIdx.z;
    const float scale = (w == 0) ? 0.125f : 1.0f;

    const int rowA = blockIdx.y * BM;
    const int rowB = blockIdx.x * BN;
    float acc[4][4][4];
    gemm_core(g_xh, g_xl, g_wh[w], g_wl[w], rowA, rowB, acc);

    const int lane = threadIdx.x & 31;
    const int wid  = threadIdx.x >> 5;
    const int wm   = wid >> 2, wn = wid & 3;
    const int r0c  = lane >> 2;
    const int cc   = (lane & 3) * 2;

    if (w == 2) {
        #pragma unroll
        for (int mf = 0; mf < 4; mf++) {
            const int mrow = rowA + wm * 64 + mf * 16;
            #pragma unroll
            for (int nf = 0; nf < 4; nf++) {
                const int col = rowB + wn * 32 + nf * 8 + cc;
                #pragma unroll
                for (int half = 0; half < 2; half++) {
                    size_t idx = (size_t)(mrow + r0c + half * 8) * DMODEL + col;
                    *(__half2*)(g_vf + idx) =
                        __floats2half2_rn(acc[mf][nf][half * 2 + 0],
                                          acc[mf][nf][half * 2 + 1]);
                }
            }
        }
    } else {
        __nv_bfloat16* H = (w == 0) ? g_qh : g_kh;
        __nv_bfloat16* L = (w == 0) ? g_ql : g_kl;
        #pragma unroll
        for (int mf = 0; mf < 4; mf++) {
            const int mrow = rowA + wm * 64 + mf * 16;
            #pragma unroll
            for (int nf = 0; nf < 4; nf++) {
                const int col = rowB + wn * 32 + nf * 8 + cc;
                #pragma unroll
                for (int half = 0; half < 2; half++) {
                    float v0 = acc[mf][nf][half * 2 + 0] * scale;
                    float v1 = acc[mf][nf][half * 2 + 1] * scale;
                    __nv_bfloat16 h0 = __float2bfloat16(v0);
                    __nv_bfloat16 h1 = __float2bfloat16(v1);
                    float l0 = v0 - __bfloat162float(h0);
                    float l1 = v1 - __bfloat162float(h1);
                    size_t idx = (size_t)(mrow + r0c + half * 8) * DMODEL + col;
                    *(__nv_bfloat162*)(H + idx) = __halves2bfloat162(h0, h1);
                    *(__nv_bfloat162*)(L + idx) = __halves2bfloat162(__float2bfloat16(l0),
                                                                     __float2bfloat16(l1));
                }
            }
        }
    }
}

__global__ void __launch_bounds__(256, 2)
gemm_out_tc(float* __restrict__ out) {
    const int rowA = blockIdx.y * BM;
    const int rowB = blockIdx.x * BN;
    float acc[4][4][4];
    gemm_core(g_ch, g_cl, g_wh[3], g_wl[3], rowA, rowB, acc);

    const int lane = threadIdx.x & 31;
    const int wid  = threadIdx.x >> 5;
    const int wm   = wid >> 2, wn = wid & 3;
    const int r0c  = lane >> 2;
    const int cc   = (lane & 3) * 2;
    #pragma unroll
    for (int mf = 0; mf < 4; mf++) {
        const int mrow = rowA + wm * 64 + mf * 16;
        #pragma unroll
        for (int nf = 0; nf < 4; nf++) {
            const int col = rowB + wn * 32 + nf * 8 + cc;
            *(float2*)(out + (size_t)(mrow + r0c) * DMODEL + col) =
                make_float2(acc[mf][nf][0], acc[mf][nf][1]);
            *(float2*)(out + (size_t)(mrow + r0c + 8) * DMODEL + col) =
                make_float2(acc[mf][nf][2], acc[mf][nf][3]);
        }
    }
}

// ================= fp32 -> bf16 hi/lo splits ===================================
__global__ void __launch_bounds__(256)
split_kernel(const float* __restrict__ in, __nv_bfloat16* __restrict__ hi,
             __nv_bfloat16* __restrict__ lo, int n4) {
    __nv_bfloat162* H = (__nv_bfloat162*)hi;
    __nv_bfloat162* L = (__nv_bfloat162*)lo;
    for (int i = blockIdx.x * blockDim.x + threadIdx.x; i < n4;
         i += gridDim.x * blockDim.x) {
        float4 v = ((const float4*)in)[i];
        float a[4] = {v.x, v.y, v.z, v.w};
        __nv_bfloat16 h[4], l[4];
        #pragma unroll
        for (int j = 0; j < 4; j++) {
            h[j] = __float2bfloat16(a[j]);
            l[j] = __float2bfloat16(a[j] - __bfloat162float(h[j]));
        }
        H[2 * i]     = __halves2bfloat162(h[0], h[1]);
        H[2 * i + 1] = __halves2bfloat162(h[2], h[3]);
        L[2 * i]     = __halves2bfloat162(l[0], l[1]);
        L[2 * i + 1] = __halves2bfloat162(l[2], l[3]);
    }
}

__global__ void __launch_bounds__(256)
split2_kernel(const float* __restrict__ in0, const float* __restrict__ in1,
              __nv_bfloat16* __restrict__ hi0, __nv_bfloat16* __restrict__ lo0,
              __nv_bfloat16* __restrict__ hi1, __nv_bfloat16* __restrict__ lo1,
              int n4) {
    const float* in = blockIdx.z ? in1 : in0;
    __nv_bfloat162* H = (__nv_bfloat162*)(blockIdx.z ? hi1 : hi0);
    __nv_bfloat162* L = (__nv_bfloat162*)(blockIdx.z ? lo1 : lo0);
    for (int i = blockIdx.x * blockDim.x + threadIdx.x; i < n4;
         i += gridDim.x * blockDim.x) {
        float4 v = ((const float4*)in)[i];
        float a[4] = {v.x, v.y, v.z, v.w};
        __nv_bfloat16 h[4], l[4];
        #pragma unroll
        for (int j = 0; j < 4; j++) {
            h[j] = __float2bfloat16(a[j]);
            l[j] = __float2bfloat16(a[j] - __bfloat162float(h[j]));
        }
        H[2 * i]     = __halves2bfloat162(h[0], h[1]);
        H[2 * i + 1] = __halves2bfloat162(h[2], h[3]);
        L[2 * i]     = __halves2bfloat162(l[0], l[1]);
        L[2 * i + 1] = __halves2bfloat162(l[2], l[3]);
    }
}

// ================= Flash attention via mma.sync (causal) =======================
#define AQROWS 128
#define ASROW  144
#define AQTILE (AQROWS * ASROW)         // 18432
#define AKTILE (64 * ASROW)             // 9216
#define ASTAGE (3 * AKTILE)             // kh, kl, vf = 27648
#define ATTN_SMEM2 (2 * AQTILE + 2 * ASTAGE)   // 92160

__device__ __forceinline__ void attn_ld_q(const __nv_bfloat16* __restrict__ g,
                                          size_t growbase, int colbase,
                                          uint32_t dst, int tid) {
    #pragma unroll
    for (int l = 0; l < 4; l++) {
        int f = tid + (l << 8);
        int r = f >> 3;
        int u = f & 7;
        cp_async16(dst + r * ASROW + u * 16,
                   g + (growbase + r) * DMODEL + colbase + u * 8);
    }
}
__device__ __forceinline__ void attn_ld_kv(const __nv_bfloat16* __restrict__ g,
                                           size_t growbase, int colbase,
                                           uint32_t dst, int tid) {
    #pragma unroll
    for (int l = 0; l < 2; l++) {
        int f = tid + (l << 8);
        int r = f >> 3;
        int u = f & 7;
        cp_async16(dst + r * ASROW + u * 16,
                   g + (growbase + r) * DMODEL + colbase + u * 8);
    }
}

__global__ void __launch_bounds__(256, 2)
attn_mma_kernel() {
    extern __shared__ __align__(128) char asmem[];
    const uint32_t sb = smem_u32(asmem);
    const uint32_t QH = sb, QL = sb + AQTILE;
    const uint32_t ST0 = sb + 2 * AQTILE;

    const int tid  = threadIdx.x;
    const int w    = tid >> 5;
    const int lane = tid & 31;
    const int qb   = (gridDim.x - 1) - blockIdx.x;
    const int bh   = blockIdx.y;
    const int b    = bh >> 4;
    const int h    = bh & 15;

    const size_t qrow = (size_t)b * SEQ + qb * AQROWS;
    const int    hcol = h * DK;
    const int    kmax = 2 * qb + 1;

    attn_ld_q(g_qh, qrow, hcol, QH, tid);
    attn_ld_q(g_ql, qrow, hcol, QL, tid);
    cp_commit_group();
    {
        size_t krow = (size_t)b * SEQ;
        attn_ld_kv(g_kh, krow, hcol, ST0 + 0 * AKTILE, tid);
        attn_ld_kv(g_kl, krow, hcol, ST0 + 1 * AKTILE, tid);
        attn_ld_kv((const __nv_bfloat16*)g_vf, krow, hcol, ST0 + 2 * AKTILE, tid);
        cp_commit_group();
    }
    cp_wait_group<0>();
    __syncthreads();

    const uint32_t a_off = (uint32_t)((w * 16 + (lane & 15)) * ASROW + (lane >> 4) * 16);
    uint32_t qh_a[4][4], ql_a[4][4];
    #pragma unroll
    for (int sk = 0; sk < 4; sk++) {
        ldsm4(qh_a[sk], QH + a_off + sk * 32);
        ldsm4(ql_a[sk], QL + a_off + sk * 32);
    }

    float o[8][4];
    #pragma unroll
    for (int f = 0; f < 8; f++)
        #pragma unroll
        for (int e = 0; e < 4; e++) o[f][e] = 0.f;
    float mA = -1e30f, mB = -1e30f, lA = 0.f, lB = 0.f;

    const uint32_t kb_off = (uint32_t)(((lane >> 4) * 8 + (lane & 7)) * ASROW
                                       + ((lane >> 3) & 1) * 16);
    const uint32_t vt_off = (uint32_t)(((lane & 7) + 8 * ((lane >> 3) & 1)) * ASROW
                                       + (lane >> 4) * 16);

    for (int kb = 0; kb <= kmax; kb++) {
        __syncthreads();
        if (kb + 1 <= kmax) {
            uint32_t st = ST0 + ((kb + 1) & 1) * ASTAGE;
            size_t krow = (size_t)b * SEQ + (size_t)(kb + 1) * 64;
            attn_ld_kv(g_kh, krow, hcol, st + 0 * AKTILE, tid);
            attn_ld_kv(g_kl, krow, hcol, st + 1 * AKTILE, tid);
            attn_ld_kv((const __nv_bfloat16*)g_vf, krow, hcol, st + 2 * AKTILE, tid);
        }
        cp_commit_group();
        cp_wait_group<1>();
        __syncthreads();

        const uint32_t st = ST0 + (kb & 1) * ASTAGE;
        const uint32_t KH = st, KL = st + AKTILE, VF = st + 2 * AKTILE;

        float s[8][4];
        #pragma unroll
        for (int f = 0; f < 8; f++)
            #pragma unroll
            for (int e = 0; e < 4; e++) s[f][e] = 0.f;

        #pragma unroll
        for (int sk = 0; sk < 4; sk++) {
            #pragma unroll
            for (int np = 0; np < 4; np++) {
                uint32_t bh4[4], bl4[4];
                uint32_t base = np * 16 * ASROW + kb_off + sk * 32;
                ldsm4(bh4, KH + base);
                ldsm4(bl4, KL + base);
                #pragma unroll
                for (int half = 0; half < 2; half++) {
                    const int nf = np * 2 + half;
                    mma16816(s[nf], qh_a[sk], bh4 + half * 2);
                    mma16816(s[nf], qh_a[sk], bl4 + half * 2);
                    mma16816(s[nf], ql_a[sk], bh4 + half * 2);
                }
            }
        }

        if (kb >= 2 * qb) {
            const int rA = w * 16 + (lane >> 2);
            const int rB = rA + 8;
            const int cbase = kb * 64 - qb * AQROWS;
            #pragma unroll
            for (int f = 0; f < 8; f++) {
                const int c0 = cbase + f * 8 + (lane & 3) * 2;
                if (c0 > rA)     s[f][0] = -1e30f;
                if (c0 + 1 > rA) s[f][1] = -1e30f;
                if (c0 > rB)     s[f][2] = -1e30f;
                if (c0 + 1 > rB) s[f][3] = -1e30f;
            }
        }

        float mAn = mA, mBn = mB;
        #pragma unroll
        for (int f = 0; f < 8; f++) {
            mAn = fmaxf(mAn, fmaxf(s[f][0], s[f][1]));
            mBn = fmaxf(mBn, fmaxf(s[f][2], s[f][3]));
        }
        mAn = fmaxf(mAn, __shfl_xor_sync(0xffffffffu, mAn, 1));
        mAn = fmaxf(mAn, __shfl_xor_sync(0xffffffffu, mAn, 2));
        mBn = fmaxf(mBn, __shfl_xor_sync(0xffffffffu, mBn, 1));
        mBn = fmaxf(mBn, __shfl_xor_sync(0xffffffffu, mBn, 2));

        const float alA = __expf(mA - mAn);
        const float alB = __expf(mB - mBn);
        float sumA = 0.f, sumB = 0.f;
        #pragma unroll
        for (int f = 0; f < 8; f++) {
            s[f][0] = __expf(s[f][0] - mAn);
            s[f][1] = __expf(s[f][1] - mAn);
            s[f][2] = __expf(s[f][2] - mBn);
            s[f][3] = __expf(s[f][3] - mBn);
            sumA += s[f][0] + s[f][1];
            sumB += s[f][2] + s[f][3];
        }
        sumA += __shfl_xor_sync(0xffffffffu, sumA, 1);
        sumA += __shfl_xor_sync(0xffffffffu, sumA, 2);
        sumB += __shfl_xor_sync(0xffffffffu, sumB, 1);
        sumB += __shfl_xor_sync(0xffffffffu, sumB, 2);
        lA = lA * alA + sumA;
        lB = lB * alB + sumB;
        mA = mAn; mB = mBn;

        #pragma unroll
        for (int f = 0; f < 8; f++) {
            o[f][0] *= alA; o[f][1] *= alA;
            o[f][2] *= alB; o[f][3] *= alB;
        }

        #pragma unroll
        for (int t = 0; t < 4; t++) {
            const int f0 = 2 * t, f1 = 2 * t + 1;
            uint32_t ap[4];
            ap[0] = pack_h16x2(s[f0][0], s[f0][1]);
            ap[1] = pack_h16x2(s[f0][2], s[f0][3]);
            ap[2] = pack_h16x2(s[f1][0], s[f1][1]);
            ap[3] = pack_h16x2(s[f1][2], s[f1][3]);
            #pragma unroll
            for (int u = 0; u < 4; u++) {
                uint32_t vf4[4];
                uint32_t base = (t * 16) * ASROW + u * 32 + vt_off;
                ldsm4t(vf4, VF + base);
                mma16816h(o[2 * u],     ap, vf4);
                mma16816h(o[2 * u + 1], ap, vf4 + 2);
            }
        }
    }

    const float invA = 1.f / fmaxf(lA, 1e-9f);
    const float invB = 1.f / fmaxf(lB, 1e-9f);
    const size_t rowA = qrow + w * 16 + (lane >> 2);
    const size_t rowB = rowA + 8;
    #pragma unroll
    for (int f = 0; f < 8; f++) {
        const int col = hcol + f * 8 + (lane & 3) * 2;
        float vA0 = o[f][0] * invA, vA1 = o[f][1] * invA;
        float vB0 = o[f][2] * invB, vB1 = o[f][3] * invB;
        __nv_bfloat16 hA0 = __float2bfloat16(vA0), hA1 = __float2bfloat16(vA1);
        __nv_bfloat16 hB0 = __float2bfloat16(vB0), hB1 = __float2bfloat16(vB1);
        *(__nv_bfloat162*)(g_ch + rowA * DMODEL + col) = __halves2bfloat162(hA0, hA1);
        *(__nv_bfloat162*)(g_ch + rowB * DMODEL + col) = __halves2bfloat162(hB0, hB1);
        *(__nv_bfloat162*)(g_cl + rowA * DMODEL + col) =
            __halves2bfloat162(__float2bfloat16(vA0 - __bfloat162float(hA0)),
                               __float2bfloat16(vA1 - __bfloat162float(hA1)));
        *(__nv_bfloat162*)(g_cl + rowB * DMODEL + col) =
            __halves2bfloat162(__float2bfloat16(vB0 - __bfloat162float(hB0)),
                               __float2bfloat16(vB1 - __bfloat162float(hB1)));
    }
}

// ================= launch ======================================================
extern "C" void kernel_launch(void* const* d_in, const int* in_sizes, int n_in,
                              void* d_out, int out_size)
{
    (void)in_sizes; (void)n_in; (void)out_size;
    const float* x  = (const float*)d_in[0];
    const float* wq = (const float*)d_in[1];
    const float* wk = (const float*)d_in[2];
    const float* wv = (const float*)d_in[3];
    const float* wo = (const float*)d_in[4];
    float* out = (float*)d_out;

    static cudaError_t a1 = cudaFuncSetAttribute(
        attn_mma_kernel, cudaFuncAttributeMaxDynamicSharedMemorySize, ATTN_SMEM2);
    static cudaError_t a2 = cudaFuncSetAttribute(
        gemm_qkv_tc, cudaFuncAttributeMaxDynamicSharedMemorySize, GEMM_SMEM);
    static cudaError_t a3 = cudaFuncSetAttribute(
        gemm_out_tc, cudaFuncAttributeMaxDynamicSharedMemorySize, GEMM_SMEM);
    (void)a1; (void)a2; (void)a3;

    __nv_bfloat16 *xh, *xl, *wh, *wl;
    cudaGetSymbolAddress((void**)&xh, g_xh);
    cudaGetSymbolAddress((void**)&xl, g_xl);
    cudaGetSymbolAddress((void**)&wh, g_wh);
    cudaGetSymbolAddress((void**)&wl, g_wl);

    const int NX = MROWS * DMODEL / 4;
    const int NW = DMODEL * DMODEL / 4;
    const size_t WSZ = (size_t)DMODEL * DMODEL;

    split_kernel<<<2048, 256>>>(x, xh, xl, NX);
    split2_kernel<<<dim3(512, 1, 2), 256>>>(wq, wk,
        wh + 0 * WSZ, wl + 0 * WSZ, wh + 1 * WSZ, wl + 1 * WSZ, NW);
    split2_kernel<<<dim3(512, 1, 2), 256>>>(wv, wo,
        wh + 2 * WSZ, wl + 2 * WSZ, wh + 3 * WSZ, wl + 3 * WSZ, NW);

    dim3 gqkv(DMODEL / BN, MROWS / BM, 3);
    gemm_qkv_tc<<<gqkv, 256, GEMM_SMEM>>>();

    dim3 gattn(SEQ / AQROWS, BATCH * NHEAD);
    attn_mma_kernel<<<gattn, 256, ATTN_SMEM2>>>();

    dim3 gout(DMODEL / BN, MROWS / BM);
    gemm_out_tc<<<gout, 256, GEMM_SMEM>>>(out);
}